// round 5
// baseline (speedup 1.0000x reference)
#include <cuda_runtime.h>
#include <cuda_bf16.h>
#include <math.h>

// ---------------- problem constants ----------------
#define L_TOK 10000
#define LP    10048          // 157 * 64 (padded length)
#define NC    157            // chunks
#define Q     64             // chunk length
#define DM    512
#define DI    1024
#define DS    64
#define NH    16
#define HD    64
#define DXBC  1152
#define DPROJ 2192
#define NB    3              // branches

// ---------------- scratch (device globals, no allocation) ----------------
__device__ __align__(16) float g_hbase[(size_t)L_TOK*DM];
__device__ __align__(16) float g_hcur [(size_t)NB*LP*DM];
__device__ __align__(16) float g_zx   [(size_t)NB*LP*DPROJ];
__device__ __align__(16) float g_xs   [(size_t)NB*LP*DI];
__device__ __align__(16) float g_Bm   [(size_t)NB*LP*DS];
__device__ __align__(16) float g_Cm   [(size_t)NB*LP*DS];
__device__ __align__(16) float g_dtv  [(size_t)NB*LP*NH];
__device__ __align__(16) float g_av   [(size_t)NB*NH*LP];
__device__ __align__(16) float g_cum  [(size_t)NB*NH*LP];
__device__ __align__(16) float g_y    [(size_t)NB*LP*DI];
__device__ __align__(16) float g_schunk[(size_t)NB*NH*NC*DS*HD];
__device__ __align__(16) float g_sbef  [(size_t)NB*NH*NC*DS*HD];
__device__ __align__(16) float g_hn   [(size_t)NB*L_TOK*DM];
__device__ __align__(16) float g_s1   [(size_t)NB*L_TOK*128];
__device__ float g_scoreb[NB*L_TOK];
__device__ float g_wts   [NB*L_TOK];
__device__ float g_pooled[DM];

// split-bf16 buffers (uint2 = {hi bf16x2, lo bf16x2} covering 2 consecutive k)
__device__ __align__(16) uint2 g_xS   [(size_t)L_TOK*512];        // 10000 x 1024/2
__device__ __align__(16) uint2 g_fc1wS[(size_t)DM*512];           // 512 x 1024/2
__device__ __align__(16) uint2 g_ipwS [(size_t)6*DPROJ*256];      // 6 x 2192 x 512/2
__device__ __align__(16) uint2 g_opwS [(size_t)6*DM*512];         // 6 x 512 x 1024/2
__device__ __align__(16) uint2 g_aw1S [(size_t)128*256];          // 128 x 512/2
__device__ __align__(16) uint2 g_hcurS[(size_t)NB*LP*256];        // 3 x 10048 x 512/2
__device__ __align__(16) uint2 g_ySp  [(size_t)NB*LP*512];        // 3 x 10048 x 1024/2
__device__ __align__(16) uint2 g_hnS  [(size_t)NB*L_TOK*256];     // 3 x 10000 x 512/2

// ---------------- helpers ----------------
__device__ __forceinline__ float bsum(float v) {
    __shared__ float sh[32];
    int lane = threadIdx.x & 31, w = threadIdx.x >> 5;
    #pragma unroll
    for (int o = 16; o > 0; o >>= 1) v += __shfl_xor_sync(0xffffffffu, v, o);
    if (lane == 0) sh[w] = v;
    __syncthreads();
    int nw = blockDim.x >> 5;
    v = (threadIdx.x < nw) ? sh[threadIdx.x] : 0.f;
    if (w == 0) {
        #pragma unroll
        for (int o = 16; o > 0; o >>= 1) v += __shfl_xor_sync(0xffffffffu, v, o);
        if (threadIdx.x == 0) sh[0] = v;
    }
    __syncthreads();
    float r = sh[0];
    __syncthreads();
    return r;
}

// ---------------- bf16 split helpers ----------------
__device__ __forceinline__ uint2 split_bf16_pair(float f0, float f1) {
    unsigned hp, lp;
    asm("cvt.rn.bf16x2.f32 %0, %1, %2;" : "=r"(hp) : "f"(f1), "f"(f0));
    __nv_bfloat162 h = *reinterpret_cast<__nv_bfloat162*>(&hp);
    float r0 = f0 - __bfloat162float(h.x);
    float r1 = f1 - __bfloat162float(h.y);
    asm("cvt.rn.bf16x2.f32 %0, %1, %2;" : "=r"(lp) : "f"(r1), "f"(r0));
    uint2 q; q.x = hp; q.y = lp;
    return q;
}

__global__ void k_split(const float* __restrict__ in, uint2* __restrict__ out, long long npairs) {
    long long i = (long long)blockIdx.x * 256 + threadIdx.x;
    if (i >= npairs) return;
    float2 v = ((const float2*)in)[i];
    out[i] = split_bf16_pair(v.x, v.y);
}

__device__ __forceinline__ void mma16(float c[4], const unsigned a[4], const unsigned b[2]) {
    asm volatile(
        "mma.sync.aligned.m16n8k16.row.col.f32.bf16.bf16.f32 "
        "{%0,%1,%2,%3},{%4,%5,%6,%7},{%8,%9},{%0,%1,%2,%3};"
        : "+f"(c[0]), "+f"(c[1]), "+f"(c[2]), "+f"(c[3])
        : "r"(a[0]), "r"(a[1]), "r"(a[2]), "r"(a[3]), "r"(b[0]), "r"(b[1]));
}

// ---------------- tensor-core GEMM on pre-split inputs ----------------
// A2[M][Kp], W2[N][Kp] of uint2{hi bf16x2, lo bf16x2}; C = A @ W^T (fp32 out)
// op: 0 = store, 1 = C += , 2 = relu(v+bias), 3 = tanh(v+bias)
// per-z: A += z*sA (pairs), C += z*sC, W += (2*z+joff)*sW (pairs)
// tiles: BM=128, BN=128, BK=16 (8 pairs); 256 threads = 8 warps (4 m x 2 n), warp tile 32x64
#define SPAD 132
__global__ __launch_bounds__(256) void tgemm(
    const uint2* __restrict__ A, long long sA,
    const uint2* __restrict__ W, long long sW,
    const float* __restrict__ bias,
    float* __restrict__ C, long long sC,
    int M, int N, int Kp, int op, int joff)
{
    int z = blockIdx.z;
    A += (long long)z * sA;
    C += (long long)z * sC;
    W += (long long)(2 * z + joff) * sW;

    __shared__ uint2 As[2][8][SPAD];
    __shared__ uint2 Ws[2][8][SPAD];

    int tid = threadIdx.x;
    int warp = tid >> 5, lane = tid & 31;
    int wm = warp & 3, wn = warp >> 2;
    int g = lane >> 2, tig = lane & 3;
    int row0 = blockIdx.y * 128, col0 = blockIdx.x * 128;

    // ldg indexing: each thread loads 4 pairs (2x uint4) for A and for W
    int ar = tid >> 1, apb = (tid & 1) * 4;
    bool aok = (row0 + ar) < M;
    bool wok = (col0 + ar) < N;
    const uint2* Aptr = A + (long long)(row0 + ar) * Kp + apb;
    const uint2* Wptr = W + (long long)(col0 + ar) * Kp + apb;

    float c[2][8][4];
    #pragma unroll
    for (int mt = 0; mt < 2; mt++)
        #pragma unroll
        for (int nt = 0; nt < 8; nt++)
            #pragma unroll
            for (int q = 0; q < 4; q++) c[mt][nt][q] = 0.f;

    uint4 pa0, pa1, pw0, pw1;
    const uint4 zu4 = make_uint4(0u, 0u, 0u, 0u);

    pa0 = aok ? *(const uint4*)(Aptr)     : zu4;
    pa1 = aok ? *(const uint4*)(Aptr + 2) : zu4;
    pw0 = wok ? *(const uint4*)(Wptr)     : zu4;
    pw1 = wok ? *(const uint4*)(Wptr + 2) : zu4;
    {
        As[0][apb + 0][ar] = make_uint2(pa0.x, pa0.y);
        As[0][apb + 1][ar] = make_uint2(pa0.z, pa0.w);
        As[0][apb + 2][ar] = make_uint2(pa1.x, pa1.y);
        As[0][apb + 3][ar] = make_uint2(pa1.z, pa1.w);
        Ws[0][apb + 0][ar] = make_uint2(pw0.x, pw0.y);
        Ws[0][apb + 1][ar] = make_uint2(pw0.z, pw0.w);
        Ws[0][apb + 2][ar] = make_uint2(pw1.x, pw1.y);
        Ws[0][apb + 3][ar] = make_uint2(pw1.z, pw1.w);
    }
    __syncthreads();

    int nK = Kp >> 3;
    for (int kt = 0; kt < nK; kt++) {
        int cur = kt & 1;
        bool pf = (kt + 1) < nK;
        if (pf) {
            const uint2* Ap = Aptr + (kt + 1) * 8;
            const uint2* Wp = Wptr + (kt + 1) * 8;
            pa0 = aok ? *(const uint4*)(Ap)     : zu4;
            pa1 = aok ? *(const uint4*)(Ap + 2) : zu4;
            pw0 = wok ? *(const uint4*)(Wp)     : zu4;
            pw1 = wok ? *(const uint4*)(Wp + 2) : zu4;
        }

        // A fragments for both m-subtiles
        uint2 qa[2][4];
        #pragma unroll
        for (int mt = 0; mt < 2; mt++) {
            int m0 = wm * 32 + mt * 16;
            qa[mt][0] = As[cur][tig    ][m0 + g    ];
            qa[mt][1] = As[cur][tig    ][m0 + g + 8];
            qa[mt][2] = As[cur][tig + 4][m0 + g    ];
            qa[mt][3] = As[cur][tig + 4][m0 + g + 8];
        }
        unsigned ahi[2][4], alo[2][4];
        #pragma unroll
        for (int mt = 0; mt < 2; mt++)
            #pragma unroll
            for (int q = 0; q < 4; q++) { ahi[mt][q] = qa[mt][q].x; alo[mt][q] = qa[mt][q].y; }

        #pragma unroll
        for (int nt = 0; nt < 8; nt++) {
            int n0 = wn * 64 + nt * 8;
            uint2 qb0 = Ws[cur][tig    ][n0 + g];
            uint2 qb1 = Ws[cur][tig + 4][n0 + g];
            unsigned bhi[2] = {qb0.x, qb1.x};
            unsigned blo[2] = {qb0.y, qb1.y};
            #pragma unroll
            for (int mt = 0; mt < 2; mt++) {
                mma16(c[mt][nt], alo[mt], bhi);
                mma16(c[mt][nt], ahi[mt], blo);
                mma16(c[mt][nt], ahi[mt], bhi);
            }
        }

        if (pf) {
            int nxt = 1 - cur;
            As[nxt][apb + 0][ar] = make_uint2(pa0.x, pa0.y);
            As[nxt][apb + 1][ar] = make_uint2(pa0.z, pa0.w);
            As[nxt][apb + 2][ar] = make_uint2(pa1.x, pa1.y);
            As[nxt][apb + 3][ar] = make_uint2(pa1.z, pa1.w);
            Ws[nxt][apb + 0][ar] = make_uint2(pw0.x, pw0.y);
            Ws[nxt][apb + 1][ar] = make_uint2(pw0.z, pw0.w);
            Ws[nxt][apb + 2][ar] = make_uint2(pw1.x, pw1.y);
            Ws[nxt][apb + 3][ar] = make_uint2(pw1.z, pw1.w);
            __syncthreads();
        }
    }

    // epilogue
    #pragma unroll
    for (int mt = 0; mt < 2; mt++) {
        #pragma unroll
        for (int nt = 0; nt < 8; nt++) {
            int cc = col0 + wn * 64 + nt * 8 + 2 * tig;
            if (cc >= N) continue;
            #pragma unroll
            for (int half = 0; half < 2; half++) {
                int r = row0 + wm * 32 + mt * 16 + g + half * 8;
                if (r >= M) continue;
                float v0 = c[mt][nt][half * 2 + 0];
                float v1 = c[mt][nt][half * 2 + 1];
                long long ci = (long long)r * N + cc;
                if (op == 0) {
                    *(float2*)&C[ci] = make_float2(v0, v1);
                } else if (op == 1) {
                    float2 o = *(float2*)&C[ci];
                    o.x += v0; o.y += v1;
                    *(float2*)&C[ci] = o;
                } else if (op == 2) {
                    v0 += bias[cc]; v1 += bias[cc + 1];
                    *(float2*)&C[ci] = make_float2(v0 > 0.f ? v0 : 0.f, v1 > 0.f ? v1 : 0.f);
                } else {
                    v0 += bias[cc]; v1 += bias[cc + 1];
                    *(float2*)&C[ci] = make_float2(tanhf(v0), tanhf(v1));
                }
            }
        }
    }
}

// ---------------- prep: build 3 branch inputs ----------------
__global__ void k_prep(const float* __restrict__ hb, float* __restrict__ hcur) {
    long long i = (long long)blockIdx.x * 256 + threadIdx.x;
    if (i >= (long long)L_TOK * DM) return;
    int t = (int)(i >> 9);
    int d = (int)(i & 511);
    float v = hb[i];
    hcur[(long long)t * DM + d] = v;                                      // branch 0
    hcur[(long long)LP * DM + (long long)t * DM + (DM - 1 - d)] = v;      // branch 1: feature flip
    int tt = (t % 100) * 100 + t / 100;                                   // branch 2: grid transpose
    hcur[2LL * LP * DM + (long long)tt * DM + d] = v;
}

__global__ void k_zeropad(float* __restrict__ hcur) {
    int i = blockIdx.x * 256 + threadIdx.x;
    const int tot = NB * (LP - L_TOK) * DM;
    if (i >= tot) return;
    int b = i / ((LP - L_TOK) * DM);
    int r = i % ((LP - L_TOK) * DM);
    hcur[(long long)b * LP * DM + (long long)L_TOK * DM + r] = 0.f;
}

// ---------------- depthwise causal conv + silu + split ----------------
__global__ void k_conv(const float* __restrict__ cw, const float* __restrict__ cb, int j) {
    int t = blockIdx.x, b = blockIdx.y;
    int lidx = 2 * b + j;
    const float* base = g_zx + (long long)b * LP * DPROJ + DI;  // xBC slice
    long long tb = (long long)b * LP + t;
    for (int c = threadIdx.x; c < DXBC; c += blockDim.x) {
        float accv = cb[lidx * DXBC + c];
        #pragma unroll
        for (int k = 0; k < 4; k++) {
            int ttk = t - 3 + k;
            if (ttk >= 0)
                accv += base[(long long)ttk * DPROJ + c] * cw[(lidx * DXBC + c) * 4 + k];
        }
        float v = accv / (1.f + __expf(-accv));
        if (t >= L_TOK) v = 0.f;
        if (c < DI)            g_xs[tb * DI + c] = v;
        else if (c < DI + DS)  g_Bm[tb * DS + (c - DI)] = v;
        else                   g_Cm[tb * DS + (c - DI - DS)] = v;
    }
}

// ---------------- dt = softplus(dt_raw + bias), a = dt * A ----------------
__global__ void k_dt(const float* __restrict__ dt_bias, const float* __restrict__ A_log, int j) {
    long long idx = (long long)blockIdx.x * 256 + threadIdx.x;
    if (idx >= (long long)NB * LP * NH) return;
    int hd = (int)(idx % NH);
    int t  = (int)((idx / NH) % LP);
    int b  = (int)(idx / ((long long)NH * LP));
    int lidx = 2 * b + j;
    float draw = g_zx[((long long)b * LP + t) * DPROJ + DI + DXBC + hd];
    float xv = draw + dt_bias[lidx * NH + hd];
    float sp = (xv > 20.f) ? xv : log1pf(expf(xv));
    if (t >= L_TOK) sp = 0.f;
    float Ah = -expf(A_log[lidx * NH + hd]);
    g_dtv[((long long)b * LP + t) * NH + hd] = sp;
    g_av[((long long)(b * NH + hd)) * LP + t] = sp * Ah;
}

// ---------------- per-chunk inclusive cumsum of a ----------------
__global__ void k_cumsum() {
    int c = blockIdx.x, h = blockIdx.y, b = blockIdx.z;
    long long base = (long long)(b * NH + h) * LP + (long long)c * Q;
    int t = threadIdx.x;  // 64 threads
    float x = g_av[base + t];
    #pragma unroll
    for (int o = 1; o < 32; o <<= 1) {
        float yv = __shfl_up_sync(0xffffffffu, x, o);
        if ((t & 31) >= o) x += yv;
    }
    __shared__ float w0;
    if (t == 31) w0 = x;
    __syncthreads();
    if (t >= 32) x += w0;
    g_cum[base + t] = x;
}

#define SMEM_INTRA ((4 * 64 * 65 + 64) * 4)

// ---------------- intra-chunk attention-like kernel + chunk state ----------------
__global__ __launch_bounds__(256) void k_intra() {
    extern __shared__ float sm[];
    float* sC   = sm;
    float* sB   = sm + 64 * 65;
    float* sU   = sm + 2 * 64 * 65;
    float* sP   = sm + 3 * 64 * 65;
    float* scum = sm + 4 * 64 * 65;

    int c = blockIdx.x, h = blockIdx.y, b = blockIdx.z;
    long long rowb = (long long)b * LP + (long long)c * Q;
    int tid = threadIdx.x;

    for (int i = tid; i < 4096; i += 256) {
        int t = i >> 6, n = i & 63;
        sC[t * 65 + n] = g_Cm[(rowb + t) * DS + n];
        sB[t * 65 + n] = g_Bm[(rowb + t) * DS + n];
        sU[t * 65 + n] = g_dtv[(rowb + t) * NH + h] * g_xs[(rowb + t) * DI + h * HD + n];
    }
    if (tid < 64) scum[tid] = g_cum[(long long)(b * NH + h) * LP + (long long)c * Q + tid];
    __syncthreads();

    int tx = tid & 15, ty = tid >> 4;
    int r0 = ty * 4, c0 = tx * 4;

    // P = mask(exp) * (C @ B^T)
    {
        float acc[4][4];
        #pragma unroll
        for (int i = 0; i < 4; i++) { acc[i][0]=0.f; acc[i][1]=0.f; acc[i][2]=0.f; acc[i][3]=0.f; }
        for (int n = 0; n < 64; n++) {
            float cv[4], bv[4];
            #pragma unroll
            for (int i = 0; i < 4; i++) cv[i] = sC[(r0 + i) * 65 + n];
            #pragma unroll
            for (int j = 0; j < 4; j++) bv[j] = sB[(c0 + j) * 65 + n];
            #pragma unroll
            for (int i = 0; i < 4; i++)
                #pragma unroll
                for (int j = 0; j < 4; j++) acc[i][j] += cv[i] * bv[j];
        }
        #pragma unroll
        for (int i = 0; i < 4; i++)
            #pragma unroll
            for (int j = 0; j < 4; j++) {
                int t = r0 + i, s = c0 + j;
                sP[t * 65 + s] = (s <= t) ? acc[i][j] * __expf(scum[t] - scum[s]) : 0.f;
            }
    }
    __syncthreads();

    // Y_intra = P @ U
    {
        float accY[4][4];
        #pragma unroll
        for (int i = 0; i < 4; i++) { accY[i][0]=0.f; accY[i][1]=0.f; accY[i][2]=0.f; accY[i][3]=0.f; }
        for (int s = 0; s < 64; s++) {
            float pv[4], uv[4];
            #pragma unroll
            for (int i = 0; i < 4; i++) pv[i] = sP[(r0 + i) * 65 + s];
            #pragma unroll
            for (int j = 0; j < 4; j++) uv[j] = sU[s * 65 + c0 + j];
            #pragma unroll
            for (int i = 0; i < 4; i++)
                #pragma unroll
                for (int j = 0; j < 4; j++) accY[i][j] += pv[i] * uv[j];
        }
        #pragma unroll
        for (int i = 0; i < 4; i++)
            #pragma unroll
            for (int j = 0; j < 4; j++)
                g_y[(rowb + r0 + i) * DI + h * HD + c0 + j] = accY[i][j];
    }

    // S_chunk[n][p] = sum_s exp(T - cum_s) B[s][n] U[s][p]
    {
        float T = scum[63];
        float accS[4][4];
        #pragma unroll
        for (int i = 0; i < 4; i++) { accS[i][0]=0.f; accS[i][1]=0.f; accS[i][2]=0.f; accS[i][3]=0.f; }
        for (int s = 0; s < 64; s++) {
            float w = __expf(T - scum[s]);
            float bv[4], uv[4];
            #pragma unroll
            for (int i = 0; i < 4; i++) bv[i] = sB[s * 65 + r0 + i] * w;
            #pragma unroll
            for (int j = 0; j < 4; j++) uv[j] = sU[s * 65 + c0 + j];
            #pragma unroll
            for (int i = 0; i < 4; i++)
                #pragma unroll
                for (int j = 0; j < 4; j++) accS[i][j] += bv[i] * uv[j];
        }
        long long sbase = ((long long)(b * NH + h) * NC + c) * 4096;
        #pragma unroll
        for (int i = 0; i < 4; i++)
            #pragma unroll
            for (int j = 0; j < 4; j++)
                g_schunk[sbase + (r0 + i) * 64 + c0 + j] = accS[i][j];
    }
}

// ---------------- sequential chunk-state recurrence (only sequential part) ----------------
__global__ __launch_bounds__(256) void k_rec() {
    int bh = blockIdx.x;          // 0..47
    int tid = threadIdx.x;        // 256
    float S[16];
    #pragma unroll
    for (int i = 0; i < 16; i++) S[i] = 0.f;
    const float* cumrow = g_cum + (long long)bh * LP;
    for (int c = 0; c < NC; c++) {
        long long base = ((long long)bh * NC + c) * 4096;
        float e = __expf(cumrow[c * Q + 63]);
        #pragma unroll
        for (int i = 0; i < 16; i++) {
            int idx = tid + i * 256;
            g_sbef[base + idx] = S[i];
            S[i] = e * S[i] + g_schunk[base + idx];
        }
    }
}

// ---------------- inter-chunk contribution + Dh*x ----------------
__global__ __launch_bounds__(256) void k_inter(const float* __restrict__ Dh, int j) {
    __shared__ float sS[64 * 65];
    __shared__ float sC[64 * 65];
    __shared__ float scum[64];
    int c = blockIdx.x, h = blockIdx.y, b = blockIdx.z;
    long long rowb = (long long)b * LP + (long long)c * Q;
    int tid = threadIdx.x;
    long long sbase = ((long long)(b * NH + h) * NC + c) * 4096;
    for (int i = tid; i < 4096; i += 256) {
        int r = i >> 6, n = i & 63;
        sS[r * 65 + n] = g_sbef[sbase + i];
        sC[r * 65 + n] = g_Cm[(rowb + r) * DS + n];
    }
    if (tid < 64) scum[tid] = g_cum[(long long)(b * NH + h) * LP + (long long)c * Q + tid];
    __syncthreads();

    int tx = tid & 15, ty = tid >> 4;
    int r0 = ty * 4, c0 = tx * 4;
    float acc[4][4];
    #pragma unroll
    for (int i = 0; i < 4; i++) { acc[i][0]=0.f; acc[i][1]=0.f; acc[i][2]=0.f; acc[i][3]=0.f; }
    for (int n = 0; n < 64; n++) {
        float cv[4], sv[4];
        #pragma unroll
        for (int i = 0; i < 4; i++) cv[i] = sC[(r0 + i) * 65 + n];
        #pragma unroll
        for (int jj = 0; jj < 4; jj++) sv[jj] = sS[n * 65 + c0 + jj];
        #pragma unroll
        for (int i = 0; i < 4; i++)
            #pragma unroll
            for (int jj = 0; jj < 4; jj++) acc[i][jj] += cv[i] * sv[jj];
    }
    float dh = Dh[(2 * b + j) * NH + h];
    #pragma unroll
    for (int i = 0; i < 4; i++) {
        float e = __expf(scum[r0 + i]);
        #pragma unroll
        for (int jj = 0; jj < 4; jj++) {
            long long ydx = (rowb + r0 + i) * DI + h * HD + c0 + jj;
            g_y[ydx] = g_y[ydx] + e * acc[i][jj] + dh * g_xs[ydx];
        }
    }
}

// ---------------- gate (silu(z)) + RMSNorm, in place on g_y ----------------
__global__ __launch_bounds__(256) void k_gate(const float* __restrict__ norm_w, int j) {
    int t = blockIdx.x, b = blockIdx.y;
    int lidx = 2 * b + j;
    const float* z = g_zx + ((long long)b * LP + t) * DPROJ;
    float* yr = g_y + ((long long)b * LP + t) * DI;
    float vals[4];
    float ss = 0.f;
    #pragma unroll
    for (int i = 0; i < 4; i++) {
        int cidx = threadIdx.x + i * 256;
        float zv = z[cidx];
        float gv = yr[cidx] * (zv / (1.f + __expf(-zv)));
        vals[i] = gv;
        ss += gv * gv;
    }
    float tot = bsum(ss);
    float scale = rsqrtf(tot / (float)DI + 1e-5f);
    #pragma unroll
    for (int i = 0; i < 4; i++) {
        int cidx = threadIdx.x + i * 256;
        yr[cidx] = vals[i] * scale * norm_w[lidx * DI + cidx];
    }
}

// ---------------- final LayerNorm over concat tokens ----------------
__global__ __launch_bounds__(256) void k_ln(const float* __restrict__ lnw, const float* __restrict__ lnb) {
    int g = blockIdx.x;          // 0..29999
    int b = g / L_TOK, t = g % L_TOK;
    const float* row = g_hcur + ((long long)b * LP + t) * DM;
    int tid = threadIdx.x;
    float v0 = row[tid], v1 = row[tid + 256];
    float s = bsum(v0 + v1);
    float sq = bsum(v0 * v0 + v1 * v1);
    float mu = s / (float)DM;
    float var = sq / (float)DM - mu * mu;
    float inv = rsqrtf(var + 1e-5f);
    g_hn[(long long)g * DM + tid]       = (v0 - mu) * inv * lnw[tid] + lnb[tid];
    g_hn[(long long)g * DM + tid + 256] = (v1 - mu) * inv * lnw[tid + 256] + lnb[tid + 256];
}

// ---------------- attention scalar score ----------------
__global__ void k_score(const float* __restrict__ w2, const float* __restrict__ b2) {
    int g = blockIdx.x;
    int tid = threadIdx.x;  // 128
    float v = g_s1[(long long)g * 128 + tid] * w2[tid];
    v = bsum(v);
    if (tid == 0) g_scoreb[g] = v + b2[0];
}

// ---------------- softmax over 30000 scores ----------------
__global__ void k_softmax() {
    const int n = NB * L_TOK;
    __shared__ float red[32];
    __shared__ float s_max, s_sum;
    int tid = threadIdx.x;  // 1024
    float m = -1e30f;
    for (int i = tid; i < n; i += 1024) m = fmaxf(m, g_scoreb[i]);
    #pragma unroll
    for (int o = 16; o > 0; o >>= 1) m = fmaxf(m, __shfl_xor_sync(0xffffffffu, m, o));
    if ((tid & 31) == 0) red[tid >> 5] = m;
    __syncthreads();
    if (tid < 32) {
        float v = red[tid];
        #pragma unroll
        for (int o = 16; o > 0; o >>= 1) v = fmaxf(v, __shfl_xor_sync(0xffffffffu, v, o));
        if (tid == 0) s_max = v;
    }
    __syncthreads();
    float m0 = s_max;
    float s = 0.f;
    for (int i = tid; i < n; i += 1024) s += expf(g_scoreb[i] - m0);
    #pragma unroll
    for (int o = 16; o > 0; o >>= 1) s += __shfl_xor_sync(0xffffffffu, s, o);
    if ((tid & 31) == 0) red[tid >> 5] = s;
    __syncthreads();
    if (tid < 32) {
        float v = red[tid];
        #pragma unroll
        for (int o = 16; o > 0; o >>= 1) v += __shfl_xor_sync(0xffffffffu, v, o);
        if (tid == 0) s_sum = v;
    }
    __syncthreads();
    float inv = 1.f / s_sum;
    for (int i = tid; i < n; i += 1024) g_wts[i] = expf(g_scoreb[i] - m0) * inv;
}

// ---------------- pooled[d] = sum_g w[g]*hn[g][d] ----------------
__global__ __launch_bounds__(256) void k_pooled() {
    int d = blockIdx.x;
    float acc = 0.f;
    for (int g = threadIdx.x; g < NB * L_TOK; g += 256)
        acc += g_wts[g] * g_hn[(long long)g * DM + d];
    acc = bsum(acc);
    if (threadIdx.x == 0) g_pooled[d] = acc;
}

// ---------------- final classifier + softmax ----------------
__global__ void k_final(const float* __restrict__ cls_w, const float* __restrict__ cls_b,
                        float* __restrict__ out, int out_size) {
    int tid = threadIdx.x;  // 64
    int cls = tid >> 5, lane = tid & 31;
    float acc = 0.f;
    for (int d = lane; d < DM; d += 32) acc += g_pooled[d] * cls_w[cls * DM + d];
    #pragma unroll
    for (int o = 16; o > 0; o >>= 1) acc += __shfl_xor_sync(0xffffffffu, acc, o);
    __shared__ float lg[2];
    if (lane == 0) lg[cls] = acc;
    __syncthreads();
    if (tid == 0) {
        float l0 = lg[0] + cls_b[0], l1 = lg[1] + cls_b[1];
        float m = fmaxf(l0, l1);
        float e0 = expf(l0 - m), e1 = expf(l1 - m);
        float s = e0 + e1;
        out[0] = l0;
        out[1] = l1;
        if (out_size >= 4) { out[2] = e0 / s; out[3] = e1 / s; }
    }
}

// ---------------- launch ----------------
static inline void launch_split(const float* src, void* dst, long long npairs) {
    k_split<<<(int)((npairs + 255) / 256), 256>>>(src, (uint2*)dst, npairs);
}

extern "C" void kernel_launch(void* const* d_in, const int* in_sizes, int n_in,
                              void* d_out, int out_size) {
    const float* x        = (const float*)d_in[0];
    const float* fc1_w    = (const float*)d_in[1];
    const float* fc1_b    = (const float*)d_in[2];
    const float* in_proj_w= (const float*)d_in[3];
    const float* conv_w   = (const float*)d_in[4];
    const float* conv_b   = (const float*)d_in[5];
    const float* dt_bias  = (const float*)d_in[6];
    const float* A_log    = (const float*)d_in[7];
    const float* Dh       = (const float*)d_in[8];
    const float* norm_w   = (const float*)d_in[9];
    const float* out_proj_w=(const float*)d_in[10];
    const float* ln_w     = (const float*)d_in[11];
    const float* ln_b     = (const float*)d_in[12];
    const float* attn_w1  = (const float*)d_in[13];
    const float* attn_b1  = (const float*)d_in[14];
    const float* attn_w2  = (const float*)d_in[15];
    const float* attn_b2  = (const float*)d_in[16];
    const float* cls_w    = (const float*)d_in[17];
    const float* cls_b    = (const float*)d_in[18];
    float* out = (float*)d_out;

    void *p_hbase, *p_hcur, *p_zx, *p_y, *p_hn, *p_s1;
    void *p_xS, *p_fc1wS, *p_ipwS, *p_opwS, *p_aw1S, *p_hcurS, *p_ySp, *p_hnS;
    cudaGetSymbolAddress(&p_hbase, g_hbase);
    cudaGetSymbolAddress(&p_hcur,  g_hcur);
    cudaGetSymbolAddress(&p_zx,    g_zx);
    cudaGetSymbolAddress(&p_y,     g_y);
    cudaGetSymbolAddress(&p_hn,    g_hn);
    cudaGetSymbolAddress(&p_s1,    g_s1);
    cudaGetSymbolAddress(&p_xS,    g_xS);
    cudaGetSymbolAddress(&p_fc1wS, g_fc1wS);
    cudaGetSymbolAddress(&p_ipwS,  g_ipwS);
    cudaGetSymbolAddress(&p_opwS,  g_opwS);
    cudaGetSymbolAddress(&p_aw1S,  g_aw1S);
    cudaGetSymbolAddress(&p_hcurS, g_hcurS);
    cudaGetSymbolAddress(&p_ySp,   g_ySp);
    cudaGetSymbolAddress(&p_hnS,   g_hnS);

    cudaFuncSetAttribute(k_intra, cudaFuncAttributeMaxDynamicSharedMemorySize, SMEM_INTRA);

    // weight + input conversions
    launch_split(x,         p_xS,    (long long)L_TOK * 512);
    launch_split(fc1_w,     p_fc1wS, (long long)DM * 512);
    launch_split(in_proj_w, p_ipwS,  (long long)6 * DPROJ * 256);
    launch_split(out_proj_w,p_opwS,  (long long)6 * DM * 512);
    launch_split(attn_w1,   p_aw1S,  (long long)128 * 256);

    // fc1: h = relu(x @ fc1_w^T + b)
    {
        dim3 grid((DM + 127) / 128, (L_TOK + 127) / 128, 1);
        tgemm<<<grid, 256>>>((const uint2*)p_xS, 0, (const uint2*)p_fc1wS, 0, fc1_b,
                             (float*)p_hbase, 0, L_TOK, DM, 512, 2, 0);
    }
    k_prep<<<(int)(((long long)L_TOK * DM + 255) / 256), 256>>>((const float*)p_hbase, (float*)p_hcur);
    k_zeropad<<<(NB * (LP - L_TOK) * DM + 255) / 256, 256>>>((float*)p_hcur);
    launch_split((const float*)p_hcur, p_hcurS, (long long)NB * LP * 256);

    for (int j = 0; j < 2; j++) {
        // in_proj: zxbcdt = h @ in_w^T (per-branch weight 2b+j)
        {
            dim3 g1((DPROJ + 127) / 128, (LP + 127) / 128, NB);
            tgemm<<<g1, 256>>>((const uint2*)p_hcurS, (long long)LP * 256,
                               (const uint2*)p_ipwS, (long long)DPROJ * 256, nullptr,
                               (float*)p_zx, (long long)LP * DPROJ,
                               LP, DPROJ, 256, 0, j);
        }
        k_conv<<<dim3(LP, NB), 128>>>(conv_w, conv_b, j);
        k_dt<<<(int)(((long long)NB * LP * NH + 255) / 256), 256>>>(dt_bias, A_log, j);
        k_cumsum<<<dim3(NC, NH, NB), 64>>>();
        k_intra<<<dim3(NC, NH, NB), 256, SMEM_INTRA>>>();
        k_rec<<<NB * NH, 256>>>();
        k_inter<<<dim3(NC, NH, NB), 256>>>(Dh, j);
        k_gate<<<dim3(LP, NB), 256>>>(norm_w, j);
        launch_split((const float*)p_y, p_ySp, (long long)NB * LP * 512);
        // out_proj + residual accumulate
        {
            dim3 g2((DM + 127) / 128, (LP + 127) / 128, NB);
            tgemm<<<g2, 256>>>((const uint2*)p_ySp, (long long)LP * 512,
                               (const uint2*)p_opwS, (long long)DM * 512, nullptr,
                               (float*)p_hcur, (long long)LP * DM,
                               LP, DM, 512, 1, j);
        }
        if (j == 0)
            launch_split((const float*)p_hcur, p_hcurS, (long long)NB * LP * 256);
    }

    // final head
    k_ln<<<NB * L_TOK, 256>>>(ln_w, ln_b);
    launch_split((const float*)p_hn, p_hnS, (long long)NB * L_TOK * 256);
    {
        dim3 ga(1, (NB * L_TOK + 127) / 128, 1);
        tgemm<<<ga, 256>>>((const uint2*)p_hnS, 0, (const uint2*)p_aw1S, 0, attn_b1,
                           (float*)p_s1, 0, NB * L_TOK, 128, 256, 3, 0);
    }
    k_score<<<NB * L_TOK, 128>>>(attn_w2, attn_b2);
    k_softmax<<<1, 1024>>>();
    k_pooled<<<DM, 256>>>();
    k_final<<<1, 64>>>(cls_w, cls_b, out, out_size);
}

// round 6
// speedup vs baseline: 1.0512x; 1.0512x over previous
#include <cuda_runtime.h>
#include <cuda_bf16.h>
#include <math.h>

// ---------------- problem constants ----------------
#define L_TOK 10000
#define LP    10048          // 157 * 64 (padded length)
#define NC    157            // chunks
#define Q     64             // chunk length
#define DM    512
#define DI    1024
#define DS    64
#define NH    16
#define HD    64
#define DXBC  1152
#define DPROJ 2192
#define NB    3              // branches

// ---------------- scratch (device globals, no allocation) ----------------
__device__ __align__(16) float g_hbase[(size_t)L_TOK*DM];
__device__ __align__(16) float g_hcur [(size_t)NB*LP*DM];
__device__ __align__(16) float g_zx   [(size_t)NB*LP*DPROJ];
__device__ __align__(16) float g_xs   [(size_t)NB*LP*DI];
__device__ __align__(16) float g_Bm   [(size_t)NB*LP*DS];
__device__ __align__(16) float g_Cm   [(size_t)NB*LP*DS];
__device__ __align__(16) float g_dtv  [(size_t)NB*LP*NH];
__device__ __align__(16) float g_av   [(size_t)NB*NH*LP];
__device__ __align__(16) float g_cum  [(size_t)NB*NH*LP];
__device__ __align__(16) float g_y    [(size_t)NB*LP*DI];
__device__ __align__(16) float g_schunk[(size_t)NB*NH*NC*DS*HD];
__device__ __align__(16) float g_sbef  [(size_t)NB*NH*NC*DS*HD];
__device__ __align__(16) float g_hn   [(size_t)NB*L_TOK*DM];
__device__ __align__(16) float g_s1   [(size_t)NB*L_TOK*128];
__device__ float g_scoreb[NB*L_TOK];
__device__ float g_wts   [NB*L_TOK];
__device__ float g_pooled[DM];

// split-bf16 buffers (uint2 = {hi bf16x2, lo bf16x2} covering 2 consecutive k)
__device__ __align__(16) uint2 g_xS   [(size_t)L_TOK*512];
__device__ __align__(16) uint2 g_fc1wS[(size_t)DM*512];
__device__ __align__(16) uint2 g_ipwS [(size_t)6*DPROJ*256];
__device__ __align__(16) uint2 g_opwS [(size_t)6*DM*512];
__device__ __align__(16) uint2 g_aw1S [(size_t)128*256];
__device__ __align__(16) uint2 g_hcurS[(size_t)NB*LP*256];
__device__ __align__(16) uint2 g_ySp  [(size_t)NB*LP*512];
__device__ __align__(16) uint2 g_hnS  [(size_t)NB*L_TOK*256];

// ---------------- helpers ----------------
__device__ __forceinline__ float bsum(float v) {
    __shared__ float sh[32];
    int lane = threadIdx.x & 31, w = threadIdx.x >> 5;
    #pragma unroll
    for (int o = 16; o > 0; o >>= 1) v += __shfl_xor_sync(0xffffffffu, v, o);
    if (lane == 0) sh[w] = v;
    __syncthreads();
    int nw = blockDim.x >> 5;
    v = (threadIdx.x < nw) ? sh[threadIdx.x] : 0.f;
    if (w == 0) {
        #pragma unroll
        for (int o = 16; o > 0; o >>= 1) v += __shfl_xor_sync(0xffffffffu, v, o);
        if (threadIdx.x == 0) sh[0] = v;
    }
    __syncthreads();
    float r = sh[0];
    __syncthreads();
    return r;
}

// ---------------- bf16 split helpers ----------------
__device__ __forceinline__ uint2 split_bf16_pair(float f0, float f1) {
    unsigned hp, lp;
    asm("cvt.rn.bf16x2.f32 %0, %1, %2;" : "=r"(hp) : "f"(f1), "f"(f0));
    __nv_bfloat162 h = *reinterpret_cast<__nv_bfloat162*>(&hp);
    float r0 = f0 - __bfloat162float(h.x);
    float r1 = f1 - __bfloat162float(h.y);
    asm("cvt.rn.bf16x2.f32 %0, %1, %2;" : "=r"(lp) : "f"(r1), "f"(r0));
    uint2 q; q.x = hp; q.y = lp;
    return q;
}

__global__ void k_split(const float* __restrict__ in, uint2* __restrict__ out, long long npairs) {
    long long i = (long long)blockIdx.x * 256 + threadIdx.x;
    if (i >= npairs) return;
    float2 v = ((const float2*)in)[i];
    out[i] = split_bf16_pair(v.x, v.y);
}

__device__ __forceinline__ void mma16(float c[4], const unsigned a[4], const unsigned b[2]) {
    asm volatile(
        "mma.sync.aligned.m16n8k16.row.col.f32.bf16.bf16.f32 "
        "{%0,%1,%2,%3},{%4,%5,%6,%7},{%8,%9},{%0,%1,%2,%3};"
        : "+f"(c[0]), "+f"(c[1]), "+f"(c[2]), "+f"(c[3])
        : "r"(a[0]), "r"(a[1]), "r"(a[2]), "r"(a[3]), "r"(b[0]), "r"(b[1]));
}

__device__ __forceinline__ void cp8(unsigned dst, const void* src, bool pred) {
    int sz = pred ? 8 : 0;
    asm volatile("cp.async.ca.shared.global [%0], [%1], 8, %2;" :: "r"(dst), "l"(src), "r"(sz));
}

// ---------------- tensor-core GEMM, cp.async 4-stage pipeline ----------------
// smem: uint4 = pairs {t, t+4} permuted so one LDS.128 = full mma fragment (hi+lo).
// op: 0 = store, 1 = C += (optionally emit split pairs to Caux), 2 = relu(v+bias), 3 = tanh(v+bias)
#define STAGES 4
#define S4 130   // uint4 row stride (2 mod 8 -> conflict-free LDS.128 phases)
#define TG_SMEM (STAGES * 4 * S4 * 16 * 2)

__global__ __launch_bounds__(256, 2) void tgemm(
    const uint2* __restrict__ A, long long sA,
    const uint2* __restrict__ W, long long sW,
    const float* __restrict__ bias,
    float* __restrict__ C, long long sC,
    uint2* __restrict__ Caux,
    int M, int N, int Kp, int op, int joff)
{
    extern __shared__ uint4 sm4[];
    uint4* As = sm4;
    uint4* Ws = sm4 + STAGES * 4 * S4;

    int z = blockIdx.z;
    A += (long long)z * sA;
    C += (long long)z * sC;
    W += (long long)(2 * z + joff) * sW;
    if (Caux) Caux += (long long)z * (sC >> 1);

    int tid = threadIdx.x;
    int warp = tid >> 5, lane = tid & 31;
    int wm = warp & 3, wn = warp >> 2;
    int g = lane >> 2, tig = lane & 3;
    int row0 = blockIdx.y * 128, col0 = blockIdx.x * 128;

    int ar = tid >> 1, half = tid & 1;
    bool aok = (row0 + ar) < M;
    bool wok = (col0 + ar) < N;
    const uint2* Ag = A + (long long)(row0 + ar) * Kp + half * 4;
    const uint2* Wg = W + (long long)(col0 + ar) * Kp + half * 4;
    unsigned aSm = (unsigned)__cvta_generic_to_shared(As);
    unsigned wSm = (unsigned)__cvta_generic_to_shared(Ws);

    float c[2][8][4];
    #pragma unroll
    for (int mt = 0; mt < 2; mt++)
        #pragma unroll
        for (int nt = 0; nt < 8; nt++)
            #pragma unroll
            for (int q = 0; q < 4; q++) c[mt][nt][q] = 0.f;

    int nK = Kp >> 3;

    // issue stage kt into slot
    #define ISSUE(kt, slot) do { \
        const uint2* _Ap = Ag + (kt) * 8; \
        const uint2* _Wp = Wg + (kt) * 8; \
        _Pragma("unroll") \
        for (int i = 0; i < 4; i++) { \
            unsigned off = (unsigned)((((slot) * 4 + i) * S4 + ar) * 16 + half * 8); \
            cp8(aSm + off, _Ap + i, aok); \
            cp8(wSm + off, _Wp + i, wok); \
        } \
    } while (0)

    #pragma unroll
    for (int s = 0; s < STAGES - 1; s++) {
        if (s < nK) ISSUE(s, s);
        asm volatile("cp.async.commit_group;");
    }

    for (int kt = 0; kt < nK; kt++) {
        asm volatile("cp.async.wait_group %0;" :: "n"(STAGES - 2));
        __syncthreads();

        int slot = kt & 3;
        const uint4* Ab = As + slot * 4 * S4;
        const uint4* Wb = Ws + slot * 4 * S4;

        uint4 fa[2][2];
        #pragma unroll
        for (int mt = 0; mt < 2; mt++) {
            int m0 = wm * 32 + mt * 16;
            fa[mt][0] = Ab[tig * S4 + m0 + g];
            fa[mt][1] = Ab[tig * S4 + m0 + g + 8];
        }
        unsigned ahi[2][4], alo[2][4];
        #pragma unroll
        for (int mt = 0; mt < 2; mt++) {
            ahi[mt][0] = fa[mt][0].x; ahi[mt][1] = fa[mt][1].x;
            ahi[mt][2] = fa[mt][0].z; ahi[mt][3] = fa[mt][1].z;
            alo[mt][0] = fa[mt][0].y; alo[mt][1] = fa[mt][1].y;
            alo[mt][2] = fa[mt][0].w; alo[mt][3] = fa[mt][1].w;
        }
        #pragma unroll
        for (int nt = 0; nt < 8; nt++) {
            int n0 = wn * 64 + nt * 8;
            uint4 fb = Wb[tig * S4 + n0 + g];
            unsigned bhi[2] = {fb.x, fb.z};
            unsigned blo[2] = {fb.y, fb.w};
            #pragma unroll
            for (int mt = 0; mt < 2; mt++) {
                mma16(c[mt][nt], alo[mt], bhi);
                mma16(c[mt][nt], ahi[mt], blo);
                mma16(c[mt][nt], ahi[mt], bhi);
            }
        }

        int pre = kt + STAGES - 1;
        if (pre < nK) ISSUE(pre, pre & 3);
        asm volatile("cp.async.commit_group;");
    }
    asm volatile("cp.async.wait_all;");

    // epilogue
    #pragma unroll
    for (int mt = 0; mt < 2; mt++) {
        #pragma unroll
        for (int nt = 0; nt < 8; nt++) {
            int cc = col0 + wn * 64 + nt * 8 + 2 * tig;
            if (cc >= N) continue;
            #pragma unroll
            for (int hf = 0; hf < 2; hf++) {
                int r = row0 + wm * 32 + mt * 16 + g + hf * 8;
                if (r >= M) continue;
                float v0 = c[mt][nt][hf * 2 + 0];
                float v1 = c[mt][nt][hf * 2 + 1];
                long long ci = (long long)r * N + cc;
                if (op == 0) {
                    *(float2*)&C[ci] = make_float2(v0, v1);
                } else if (op == 1) {
                    float2 o = *(float2*)&C[ci];
                    o.x += v0; o.y += v1;
                    *(float2*)&C[ci] = o;
                    if (Caux) Caux[ci >> 1] = split_bf16_pair(o.x, o.y);
                } else if (op == 2) {
                    v0 += bias[cc]; v1 += bias[cc + 1];
                    *(float2*)&C[ci] = make_float2(v0 > 0.f ? v0 : 0.f, v1 > 0.f ? v1 : 0.f);
                } else {
                    v0 += bias[cc]; v1 += bias[cc + 1];
                    *(float2*)&C[ci] = make_float2(tanhf(v0), tanhf(v1));
                }
            }
        }
    }
    #undef ISSUE
}

// ---------------- prep: build 3 branch inputs ----------------
__global__ void k_prep(const float* __restrict__ hb, float* __restrict__ hcur) {
    long long i = (long long)blockIdx.x * 256 + threadIdx.x;
    if (i >= (long long)L_TOK * DM) return;
    int t = (int)(i >> 9);
    int d = (int)(i & 511);
    float v = hb[i];
    hcur[(long long)t * DM + d] = v;
    hcur[(long long)LP * DM + (long long)t * DM + (DM - 1 - d)] = v;
    int tt = (t % 100) * 100 + t / 100;
    hcur[2LL * LP * DM + (long long)tt * DM + d] = v;
}

__global__ void k_zeropad(float* __restrict__ hcur) {
    int i = blockIdx.x * 256 + threadIdx.x;
    const int tot = NB * (LP - L_TOK) * DM;
    if (i >= tot) return;
    int b = i / ((LP - L_TOK) * DM);
    int r = i % ((LP - L_TOK) * DM);
    hcur[(long long)b * LP * DM + (long long)L_TOK * DM + r] = 0.f;
}

// ---------------- depthwise causal conv + silu + split ----------------
__global__ void k_conv(const float* __restrict__ cw, const float* __restrict__ cb, int j) {
    int t = blockIdx.x, b = blockIdx.y;
    int lidx = 2 * b + j;
    const float* base = g_zx + (long long)b * LP * DPROJ + DI;
    long long tb = (long long)b * LP + t;
    for (int c = threadIdx.x; c < DXBC; c += blockDim.x) {
        float accv = cb[lidx * DXBC + c];
        #pragma unroll
        for (int k = 0; k < 4; k++) {
            int ttk = t - 3 + k;
            if (ttk >= 0)
                accv += base[(long long)ttk * DPROJ + c] * cw[(lidx * DXBC + c) * 4 + k];
        }
        float v = accv / (1.f + __expf(-accv));
        if (t >= L_TOK) v = 0.f;
        if (c < DI)            g_xs[tb * DI + c] = v;
        else if (c < DI + DS)  g_Bm[tb * DS + (c - DI)] = v;
        else                   g_Cm[tb * DS + (c - DI - DS)] = v;
    }
}

// ---------------- dt = softplus(dt_raw + bias), a = dt * A ----------------
__global__ void k_dt(const float* __restrict__ dt_bias, const float* __restrict__ A_log, int j) {
    long long idx = (long long)blockIdx.x * 256 + threadIdx.x;
    if (idx >= (long long)NB * LP * NH) return;
    int hd = (int)(idx % NH);
    int t  = (int)((idx / NH) % LP);
    int b  = (int)(idx / ((long long)NH * LP));
    int lidx = 2 * b + j;
    float draw = g_zx[((long long)b * LP + t) * DPROJ + DI + DXBC + hd];
    float xv = draw + dt_bias[lidx * NH + hd];
    float sp = (xv > 20.f) ? xv : log1pf(expf(xv));
    if (t >= L_TOK) sp = 0.f;
    float Ah = -expf(A_log[lidx * NH + hd]);
    g_dtv[((long long)b * LP + t) * NH + hd] = sp;
    g_av[((long long)(b * NH + hd)) * LP + t] = sp * Ah;
}

// ---------------- per-chunk inclusive cumsum of a ----------------
__global__ void k_cumsum() {
    int c = blockIdx.x, h = blockIdx.y, b = blockIdx.z;
    long long base = (long long)(b * NH + h) * LP + (long long)c * Q;
    int t = threadIdx.x;
    float x = g_av[base + t];
    #pragma unroll
    for (int o = 1; o < 32; o <<= 1) {
        float yv = __shfl_up_sync(0xffffffffu, x, o);
        if ((t & 31) >= o) x += yv;
    }
    __shared__ float w0;
    if (t == 31) w0 = x;
    __syncthreads();
    if (t >= 32) x += w0;
    g_cum[base + t] = x;
}

#define SMEM_INTRA ((4 * 64 * 65 + 64) * 4)

// ---------------- intra-chunk attention-like kernel + chunk state ----------------
__global__ __launch_bounds__(256) void k_intra() {
    extern __shared__ float sm[];
    float* sC   = sm;
    float* sB   = sm + 64 * 65;
    float* sU   = sm + 2 * 64 * 65;
    float* sP   = sm + 3 * 64 * 65;
    float* scum = sm + 4 * 64 * 65;

    int c = blockIdx.x, h = blockIdx.y, b = blockIdx.z;
    long long rowb = (long long)b * LP + (long long)c * Q;
    int tid = threadIdx.x;

    for (int i = tid; i < 4096; i += 256) {
        int t = i >> 6, n = i & 63;
        sC[t * 65 + n] = g_Cm[(rowb + t) * DS + n];
        sB[t * 65 + n] = g_Bm[(rowb + t) * DS + n];
        sU[t * 65 + n] = g_dtv[(rowb + t) * NH + h] * g_xs[(rowb + t) * DI + h * HD + n];
    }
    if (tid < 64) scum[tid] = g_cum[(long long)(b * NH + h) * LP + (long long)c * Q + tid];
    __syncthreads();

    int tx = tid & 15, ty = tid >> 4;
    int r0 = ty * 4, c0 = tx * 4;

    {
        float acc[4][4];
        #pragma unroll
        for (int i = 0; i < 4; i++) { acc[i][0]=0.f; acc[i][1]=0.f; acc[i][2]=0.f; acc[i][3]=0.f; }
        for (int n = 0; n < 64; n++) {
            float cv[4], bv[4];
            #pragma unroll
            for (int i = 0; i < 4; i++) cv[i] = sC[(r0 + i) * 65 + n];
            #pragma unroll
            for (int j = 0; j < 4; j++) bv[j] = sB[(c0 + j) * 65 + n];
            #pragma unroll
            for (int i = 0; i < 4; i++)
                #pragma unroll
                for (int j = 0; j < 4; j++) acc[i][j] += cv[i] * bv[j];
        }
        #pragma unroll
        for (int i = 0; i < 4; i++)
            #pragma unroll
            for (int j = 0; j < 4; j++) {
                int t = r0 + i, s = c0 + j;
                sP[t * 65 + s] = (s <= t) ? acc[i][j] * __expf(scum[t] - scum[s]) : 0.f;
            }
    }
    __syncthreads();

    {
        float accY[4][4];
        #pragma unroll
        for (int i = 0; i < 4; i++) { accY[i][0]=0.f; accY[i][1]=0.f; accY[i][2]=0.f; accY[i][3]=0.f; }
        for (int s = 0; s < 64; s++) {
            float pv[4], uv[4];
            #pragma unroll
            for (int i = 0; i < 4; i++) pv[i] = sP[(r0 + i) * 65 + s];
            #pragma unroll
            for (int j = 0; j < 4; j++) uv[j] = sU[s * 65 + c0 + j];
            #pragma unroll
            for (int i = 0; i < 4; i++)
                #pragma unroll
                for (int j = 0; j < 4; j++) accY[i][j] += pv[i] * uv[j];
        }
        #pragma unroll
        for (int i = 0; i < 4; i++)
            #pragma unroll
            for (int j = 0; j < 4; j++)
                g_y[(rowb + r0 + i) * DI + h * HD + c0 + j] = accY[i][j];
    }

    {
        float T = scum[63];
        float accS[4][4];
        #pragma unroll
        for (int i = 0; i < 4; i++) { accS[i][0]=0.f; accS[i][1]=0.f; accS[i][2]=0.f; accS[i][3]=0.f; }
        for (int s = 0; s < 64; s++) {
            float w = __expf(T - scum[s]);
            float bv[4], uv[4];
            #pragma unroll
            for (int i = 0; i < 4; i++) bv[i] = sB[s * 65 + r0 + i] * w;
            #pragma unroll
            for (int j = 0; j < 4; j++) uv[j] = sU[s * 65 + c0 + j];
            #pragma unroll
            for (int i = 0; i < 4; i++)
                #pragma unroll
                for (int j = 0; j < 4; j++) accS[i][j] += bv[i] * uv[j];
        }
        long long sbase = ((long long)(b * NH + h) * NC + c) * 4096;
        #pragma unroll
        for (int i = 0; i < 4; i++)
            #pragma unroll
            for (int j = 0; j < 4; j++)
                g_schunk[sbase + (r0 + i) * 64 + c0 + j] = accS[i][j];
    }
}

// ---------------- sequential chunk-state recurrence ----------------
__global__ __launch_bounds__(256) void k_rec() {
    int bh = blockIdx.x;
    int tid = threadIdx.x;
    float S[16];
    #pragma unroll
    for (int i = 0; i < 16; i++) S[i] = 0.f;
    const float* cumrow = g_cum + (long long)bh * LP;
    for (int c = 0; c < NC; c++) {
        long long base = ((long long)bh * NC + c) * 4096;
        float e = __expf(cumrow[c * Q + 63]);
        #pragma unroll
        for (int i = 0; i < 16; i++) {
            int idx = tid + i * 256;
            g_sbef[base + idx] = S[i];
            S[i] = e * S[i] + g_schunk[base + idx];
        }
    }
}

// ---------------- inter-chunk contribution + Dh*x ----------------
__global__ __launch_bounds__(256) void k_inter(const float* __restrict__ Dh, int j) {
    __shared__ float sS[64 * 65];
    __shared__ float sC[64 * 65];
    __shared__ float scum[64];
    int c = blockIdx.x, h = blockIdx.y, b = blockIdx.z;
    long long rowb = (long long)b * LP + (long long)c * Q;
    int tid = threadIdx.x;
    long long sbase = ((long long)(b * NH + h) * NC + c) * 4096;
    for (int i = tid; i < 4096; i += 256) {
        int r = i >> 6, n = i & 63;
        sS[r * 65 + n] = g_sbef[sbase + i];
        sC[r * 65 + n] = g_Cm[(rowb + r) * DS + n];
    }
    if (tid < 64) scum[tid] = g_cum[(long long)(b * NH + h) * LP + (long long)c * Q + tid];
    __syncthreads();

    int tx = tid & 15, ty = tid >> 4;
    int r0 = ty * 4, c0 = tx * 4;
    float acc[4][4];
    #pragma unroll
    for (int i = 0; i < 4; i++) { acc[i][0]=0.f; acc[i][1]=0.f; acc[i][2]=0.f; acc[i][3]=0.f; }
    for (int n = 0; n < 64; n++) {
        float cv[4], sv[4];
        #pragma unroll
        for (int i = 0; i < 4; i++) cv[i] = sC[(r0 + i) * 65 + n];
        #pragma unroll
        for (int jj = 0; jj < 4; jj++) sv[jj] = sS[n * 65 + c0 + jj];
        #pragma unroll
        for (int i = 0; i < 4; i++)
            #pragma unroll
            for (int jj = 0; jj < 4; jj++) acc[i][jj] += cv[i] * sv[jj];
    }
    float dh = Dh[(2 * b + j) * NH + h];
    #pragma unroll
    for (int i = 0; i < 4; i++) {
        float e = __expf(scum[r0 + i]);
        #pragma unroll
        for (int jj = 0; jj < 4; jj++) {
            long long ydx = (rowb + r0 + i) * DI + h * HD + c0 + jj;
            g_y[ydx] = g_y[ydx] + e * acc[i][jj] + dh * g_xs[ydx];
        }
    }
}

// ---------------- gate (silu(z)) + RMSNorm, writes split pairs directly ----------------
__global__ __launch_bounds__(256) void k_gate(const float* __restrict__ norm_w, int j) {
    int t = blockIdx.x, b = blockIdx.y;
    int lidx = 2 * b + j;
    const float* z = g_zx + ((long long)b * LP + t) * DPROJ;
    const float* yr = g_y + ((long long)b * LP + t) * DI;
    uint2* yo = g_ySp + ((long long)b * LP + t) * 512;
    int c0 = threadIdx.x * 4;
    float4 zv4 = *(const float4*)&z[c0];
    float4 yv4 = *(const float4*)&yr[c0];
    float vals[4];
    float zv[4] = {zv4.x, zv4.y, zv4.z, zv4.w};
    float yv[4] = {yv4.x, yv4.y, yv4.z, yv4.w};
    float ss = 0.f;
    #pragma unroll
    for (int i = 0; i < 4; i++) {
        float gv = yv[i] * (zv[i] / (1.f + __expf(-zv[i])));
        vals[i] = gv;
        ss += gv * gv;
    }
    float tot = bsum(ss);
    float scale = rsqrtf(tot / (float)DI + 1e-5f);
    float4 nw4 = *(const float4*)&norm_w[lidx * DI + c0];
    float nw[4] = {nw4.x, nw4.y, nw4.z, nw4.w};
    #pragma unroll
    for (int p = 0; p < 2; p++) {
        float v0 = vals[2 * p]     * scale * nw[2 * p];
        float v1 = vals[2 * p + 1] * scale * nw[2 * p + 1];
        yo[(c0 >> 1) + p] = split_bf16_pair(v0, v1);
    }
}

// ---------------- final LayerNorm: writes fp32 hn + split pairs ----------------
__global__ __launch_bounds__(256) void k_ln(const float* __restrict__ lnw, const float* __restrict__ lnb) {
    int g = blockIdx.x;          // 0..29999
    int b = g / L_TOK, t = g % L_TOK;
    const float* row = g_hcur + ((long long)b * LP + t) * DM;
    int tid = threadIdx.x;
    float2 v = *(const float2*)&row[2 * tid];
    float s = bsum(v.x + v.y);
    float sq = bsum(v.x * v.x + v.y * v.y);
    float mu = s / (float)DM;
    float var = sq / (float)DM - mu * mu;
    float inv = rsqrtf(var + 1e-5f);
    float o0 = (v.x - mu) * inv * lnw[2 * tid]     + lnb[2 * tid];
    float o1 = (v.y - mu) * inv * lnw[2 * tid + 1] + lnb[2 * tid + 1];
    *(float2*)&g_hn[(long long)g * DM + 2 * tid] = make_float2(o0, o1);
    g_hnS[(long long)g * 256 + tid] = split_bf16_pair(o0, o1);
}

// ---------------- attention scalar score ----------------
__global__ void k_score(const float* __restrict__ w2, const float* __restrict__ b2) {
    int g = blockIdx.x;
    int tid = threadIdx.x;
    float v = g_s1[(long long)g * 128 + tid] * w2[tid];
    v = bsum(v);
    if (tid == 0) g_scoreb[g] = v + b2[0];
}

// ---------------- softmax over 30000 scores ----------------
__global__ void k_softmax() {
    const int n = NB * L_TOK;
    __shared__ float red[32];
    __shared__ float s_max, s_sum;
    int tid = threadIdx.x;
    float m = -1e30f;
    for (int i = tid; i < n; i += 1024) m = fmaxf(m, g_scoreb[i]);
    #pragma unroll
    for (int o = 16; o > 0; o >>= 1) m = fmaxf(m, __shfl_xor_sync(0xffffffffu, m, o));
    if ((tid & 31) == 0) red[tid >> 5] = m;
    __syncthreads();
    if (tid < 32) {
        float v = red[tid];
        #pragma unroll
        for (int o = 16; o > 0; o >>= 1) v = fmaxf(v, __shfl_xor_sync(0xffffffffu, v, o));
        if (tid == 0) s_max = v;
    }
    __syncthreads();
    float m0 = s_max;
    float s = 0.f;
    for (int i = tid; i < n; i += 1024) s += expf(g_scoreb[i] - m0);
    #pragma unroll
    for (int o = 16; o > 0; o >>= 1) s += __shfl_xor_sync(0xffffffffu, s, o);
    if ((tid & 31) == 0) red[tid >> 5] = s;
    __syncthreads();
    if (tid < 32) {
        float v = red[tid];
        #pragma unroll
        for (int o = 16; o > 0; o >>= 1) v += __shfl_xor_sync(0xffffffffu, v, o);
        if (tid == 0) s_sum = v;
    }
    __syncthreads();
    float inv = 1.f / s_sum;
    for (int i = tid; i < n; i += 1024) g_wts[i] = expf(g_scoreb[i] - m0) * inv;
}

// ---------------- pooled[d] = sum_g w[g]*hn[g][d] ----------------
__global__ __launch_bounds__(256) void k_pooled() {
    int d = blockIdx.x;
    float acc = 0.f;
    for (int g = threadIdx.x; g < NB * L_TOK; g += 256)
        acc += g_wts[g] * g_hn[(long long)g * DM + d];
    acc = bsum(acc);
    if (threadIdx.x == 0) g_pooled[d] = acc;
}

// ---------------- final classifier + softmax ----------------
__global__ void k_final(const float* __restrict__ cls_w, const float* __restrict__ cls_b,
                        float* __restrict__ out, int out_size) {
    int tid = threadIdx.x;
    int cls = tid >> 5, lane = tid & 31;
    float acc = 0.f;
    for (int d = lane; d < DM; d += 32) acc += g_pooled[d] * cls_w[cls * DM + d];
    #pragma unroll
    for (int o = 16; o > 0; o >>= 1) acc += __shfl_xor_sync(0xffffffffu, acc, o);
    __shared__ float lg[2];
    if (lane == 0) lg[cls] = acc;
    __syncthreads();
    if (tid == 0) {
        float l0 = lg[0] + cls_b[0], l1 = lg[1] + cls_b[1];
        float m = fmaxf(l0, l1);
        float e0 = expf(l0 - m), e1 = expf(l1 - m);
        float s = e0 + e1;
        out[0] = l0;
        out[1] = l1;
        if (out_size >= 4) { out[2] = e0 / s; out[3] = e1 / s; }
    }
}

// ---------------- launch ----------------
static inline void launch_split(const float* src, void* dst, long long npairs) {
    k_split<<<(int)((npairs + 255) / 256), 256>>>(src, (uint2*)dst, npairs);
}

extern "C" void kernel_launch(void* const* d_in, const int* in_sizes, int n_in,
                              void* d_out, int out_size) {
    const float* x        = (const float*)d_in[0];
    const float* fc1_w    = (const float*)d_in[1];
    const float* fc1_b    = (const float*)d_in[2];
    const float* in_proj_w= (const float*)d_in[3];
    const float* conv_w   = (const float*)d_in[4];
    const float* conv_b   = (const float*)d_in[5];
    const float* dt_bias  = (const float*)d_in[6];
    const float* A_log    = (const float*)d_in[7];
    const float* Dh       = (const float*)d_in[8];
    const float* norm_w   = (const float*)d_in[9];
    const float* out_proj_w=(const float*)d_in[10];
    const float* ln_w     = (const float*)d_in[11];
    const float* ln_b     = (const float*)d_in[12];
    const float* attn_w1  = (const float*)d_in[13];
    const float* attn_b1  = (const float*)d_in[14];
    const float* attn_w2  = (const float*)d_in[15];
    const float* attn_b2  = (const float*)d_in[16];
    const float* cls_w    = (const float*)d_in[17];
    const float* cls_b    = (const float*)d_in[18];
    float* out = (float*)d_out;

    void *p_hbase, *p_hcur, *p_zx, *p_y, *p_hn, *p_s1;
    void *p_xS, *p_fc1wS, *p_ipwS, *p_opwS, *p_aw1S, *p_hcurS, *p_ySp, *p_hnS;
    cudaGetSymbolAddress(&p_hbase, g_hbase);
    cudaGetSymbolAddress(&p_hcur,  g_hcur);
    cudaGetSymbolAddress(&p_zx,    g_zx);
    cudaGetSymbolAddress(&p_y,     g_y);
    cudaGetSymbolAddress(&p_hn,    g_hn);
    cudaGetSymbolAddress(&p_s1,    g_s1);
    cudaGetSymbolAddress(&p_xS,    g_xS);
    cudaGetSymbolAddress(&p_fc1wS, g_fc1wS);
    cudaGetSymbolAddress(&p_ipwS,  g_ipwS);
    cudaGetSymbolAddress(&p_opwS,  g_opwS);
    cudaGetSymbolAddress(&p_aw1S,  g_aw1S);
    cudaGetSymbolAddress(&p_hcurS, g_hcurS);
    cudaGetSymbolAddress(&p_ySp,   g_ySp);
    cudaGetSymbolAddress(&p_hnS,   g_hnS);

    cudaFuncSetAttribute(k_intra, cudaFuncAttributeMaxDynamicSharedMemorySize, SMEM_INTRA);
    cudaFuncSetAttribute(tgemm,   cudaFuncAttributeMaxDynamicSharedMemorySize, TG_SMEM);

    // weight + input conversions
    launch_split(x,         p_xS,    (long long)L_TOK * 512);
    launch_split(fc1_w,     p_fc1wS, (long long)DM * 512);
    launch_split(in_proj_w, p_ipwS,  (long long)6 * DPROJ * 256);
    launch_split(out_proj_w,p_opwS,  (long long)6 * DM * 512);
    launch_split(attn_w1,   p_aw1S,  (long long)128 * 256);

    // fc1: h = relu(x @ fc1_w^T + b)
    {
        dim3 grid((DM + 127) / 128, (L_TOK + 127) / 128, 1);
        tgemm<<<grid, 256, TG_SMEM>>>((const uint2*)p_xS, 0, (const uint2*)p_fc1wS, 0, fc1_b,
                                      (float*)p_hbase, 0, nullptr, L_TOK, DM, 512, 2, 0);
    }
    k_prep<<<(int)(((long long)L_TOK * DM + 255) / 256), 256>>>((const float*)p_hbase, (float*)p_hcur);
    k_zeropad<<<(NB * (LP - L_TOK) * DM + 255) / 256, 256>>>((float*)p_hcur);
    launch_split((const float*)p_hcur, p_hcurS, (long long)NB * LP * 256);

    for (int j = 0; j < 2; j++) {
        // in_proj
        {
            dim3 g1((DPROJ + 127) / 128, (LP + 127) / 128, NB);
            tgemm<<<g1, 256, TG_SMEM>>>((const uint2*)p_hcurS, (long long)LP * 256,
                                        (const uint2*)p_ipwS, (long long)DPROJ * 256, nullptr,
                                        (float*)p_zx, (long long)LP * DPROJ, nullptr,
                                        LP, DPROJ, 256, 0, j);
        }
        k_conv<<<dim3(LP, NB), 128>>>(conv_w, conv_b, j);
        k_dt<<<(int)(((long long)NB * LP * NH + 255) / 256), 256>>>(dt_bias, A_log, j);
        k_cumsum<<<dim3(NC, NH, NB), 64>>>();
        k_intra<<<dim3(NC, NH, NB), 256, SMEM_INTRA>>>();
        k_rec<<<NB * NH, 256>>>();
        k_inter<<<dim3(NC, NH, NB), 256>>>(Dh, j);
        k_gate<<<dim3(LP, NB), 256>>>(norm_w, j);
        // out_proj + residual accumulate (+ fused split of updated hcur for next layer)
        {
            dim3 g2((DM + 127) / 128, (LP + 127) / 128, NB);
            tgemm<<<g2, 256, TG_SMEM>>>((const uint2*)p_ySp, (long long)LP * 512,
                                        (const uint2*)p_opwS, (long long)DM * 512, nullptr,
                                        (float*)p_hcur, (long long)LP * DM,
                                        (j == 0) ? (uint2*)p_hcurS : nullptr,
                                        LP, DM, 512, 1, j);
        }
    }

    // final head
    k_ln<<<NB * L_TOK, 256>>>(ln_w, ln_b);
    {
        dim3 ga(1, (NB * L_TOK + 127) / 128, 1);
        tgemm<<<ga, 256, TG_SMEM>>>((const uint2*)p_hnS, 0, (const uint2*)p_aw1S, 0, attn_b1,
                                    (float*)p_s1, 0, nullptr, NB * L_TOK, 128, 256, 3, 0);
    }
    k_score<<<NB * L_TOK, 128>>>(attn_w2, attn_b2);
    k_softmax<<<1, 1024>>>();
    k_pooled<<<DM, 256>>>();
    k_final<<<1, 64>>>(cls_w, cls_b, out, out_size);
}

// round 7
// speedup vs baseline: 1.0542x; 1.0029x over previous
#include <cuda_runtime.h>
#include <cuda_bf16.h>
#include <math.h>

// ---------------- problem constants ----------------
#define L_TOK 10000
#define LP    10048          // 157 * 64 (padded length)
#define NC    157            // chunks
#define Q     64             // chunk length
#define DM    512
#define DI    1024
#define DS    64
#define NH    16
#define HD    64
#define DXBC  1152
#define DPROJ 2192
#define NB    3              // branches

// ---------------- scratch (device globals, no allocation) ----------------
__device__ __align__(16) float g_hbase[(size_t)L_TOK*DM];
__device__ __align__(16) float g_hcur [(size_t)NB*LP*DM];
__device__ __align__(16) float g_zx   [(size_t)NB*LP*DPROJ];
__device__ __align__(16) float g_xs   [(size_t)NB*LP*DI];
__device__ __align__(16) float g_Bm   [(size_t)NB*LP*DS];
__device__ __align__(16) float g_Cm   [(size_t)NB*LP*DS];
__device__ __align__(16) float g_dtv  [(size_t)NB*LP*NH];
__device__ __align__(16) float g_av   [(size_t)NB*NH*LP];
__device__ __align__(16) float g_cum  [(size_t)NB*NH*LP];
__device__ __align__(16) float g_y    [(size_t)NB*LP*DI];
__device__ __align__(16) float g_schunk[(size_t)NB*NH*NC*DS*HD];
__device__ __align__(16) float g_sbef  [(size_t)NB*NH*NC*DS*HD];
__device__ __align__(16) float g_hn   [(size_t)NB*L_TOK*DM];
__device__ __align__(16) float g_s1   [(size_t)NB*L_TOK*128];
__device__ float g_scoreb[NB*L_TOK];
__device__ float g_wts   [NB*L_TOK];
__device__ float g_pooled[DM];

// split-bf16 buffers (uint2 = {hi bf16x2, lo bf16x2} covering 2 consecutive k)
__device__ __align__(16) uint2 g_xS   [(size_t)L_TOK*512];
__device__ __align__(16) uint2 g_fc1wS[(size_t)DM*512];
__device__ __align__(16) uint2 g_ipwS [(size_t)6*DPROJ*256];
__device__ __align__(16) uint2 g_opwS [(size_t)6*DM*512];
__device__ __align__(16) uint2 g_aw1S [(size_t)128*256];
__device__ __align__(16) uint2 g_hcurS[(size_t)NB*LP*256];
__device__ __align__(16) uint2 g_ySp  [(size_t)NB*LP*512];
__device__ __align__(16) uint2 g_hnS  [(size_t)NB*L_TOK*256];

// ---------------- helpers ----------------
__device__ __forceinline__ float bsum(float v) {
    __shared__ float sh[32];
    int lane = threadIdx.x & 31, w = threadIdx.x >> 5;
    #pragma unroll
    for (int o = 16; o > 0; o >>= 1) v += __shfl_xor_sync(0xffffffffu, v, o);
    if (lane == 0) sh[w] = v;
    __syncthreads();
    int nw = blockDim.x >> 5;
    v = (threadIdx.x < nw) ? sh[threadIdx.x] : 0.f;
    if (w == 0) {
        #pragma unroll
        for (int o = 16; o > 0; o >>= 1) v += __shfl_xor_sync(0xffffffffu, v, o);
        if (threadIdx.x == 0) sh[0] = v;
    }
    __syncthreads();
    float r = sh[0];
    __syncthreads();
    return r;
}

// ---------------- bf16 split helpers ----------------
__device__ __forceinline__ uint2 split_bf16_pair(float f0, float f1) {
    unsigned hp, lp;
    asm("cvt.rn.bf16x2.f32 %0, %1, %2;" : "=r"(hp) : "f"(f1), "f"(f0));
    __nv_bfloat162 h = *reinterpret_cast<__nv_bfloat162*>(&hp);
    float r0 = f0 - __bfloat162float(h.x);
    float r1 = f1 - __bfloat162float(h.y);
    asm("cvt.rn.bf16x2.f32 %0, %1, %2;" : "=r"(lp) : "f"(r1), "f"(r0));
    uint2 q; q.x = hp; q.y = lp;
    return q;
}

__global__ void k_split(const float* __restrict__ in, uint2* __restrict__ out, long long npairs) {
    long long i = (long long)blockIdx.x * 256 + threadIdx.x;
    if (i >= npairs) return;
    float2 v = ((const float2*)in)[i];
    out[i] = split_bf16_pair(v.x, v.y);
}

__device__ __forceinline__ void mma16(float c[4], const unsigned a[4], const unsigned b[2]) {
    asm volatile(
        "mma.sync.aligned.m16n8k16.row.col.f32.bf16.bf16.f32 "
        "{%0,%1,%2,%3},{%4,%5,%6,%7},{%8,%9},{%0,%1,%2,%3};"
        : "+f"(c[0]), "+f"(c[1]), "+f"(c[2]), "+f"(c[3])
        : "r"(a[0]), "r"(a[1]), "r"(a[2]), "r"(a[3]), "r"(b[0]), "r"(b[1]));
}

__device__ __forceinline__ void cp8(unsigned dst, const void* src, bool pred) {
    int sz = pred ? 8 : 0;
    asm volatile("cp.async.ca.shared.global [%0], [%1], 8, %2;" :: "r"(dst), "l"(src), "r"(sz));
}

// ---------------- tensor-core GEMM, cp.async 4-stage pipeline ----------------
#define STAGES 4
#define S4 130
#define TG_SMEM (STAGES * 4 * S4 * 16 * 2)

__global__ __launch_bounds__(256, 2) void tgemm(
    const uint2* __restrict__ A, long long sA,
    const uint2* __restrict__ W, long long sW,
    const float* __restrict__ bias,
    float* __restrict__ C, long long sC,
    uint2* __restrict__ Caux,
    int M, int N, int Kp, int op, int joff)
{
    extern __shared__ uint4 sm4[];
    uint4* As = sm4;
    uint4* Ws = sm4 + STAGES * 4 * S4;

    int z = blockIdx.z;
    A += (long long)z * sA;
    C += (long long)z * sC;
    W += (long long)(2 * z + joff) * sW;
    if (Caux) Caux += (long long)z * (sC >> 1);

    int tid = threadIdx.x;
    int warp = tid >> 5, lane = tid & 31;
    int wm = warp & 3, wn = warp >> 2;
    int g = lane >> 2, tig = lane & 3;
    int row0 = blockIdx.y * 128, col0 = blockIdx.x * 128;

    int ar = tid >> 1, half = tid & 1;
    bool aok = (row0 + ar) < M;
    bool wok = (col0 + ar) < N;
    const uint2* Ag = A + (long long)(row0 + ar) * Kp + half * 4;
    const uint2* Wg = W + (long long)(col0 + ar) * Kp + half * 4;
    unsigned aSm = (unsigned)__cvta_generic_to_shared(As);
    unsigned wSm = (unsigned)__cvta_generic_to_shared(Ws);

    float c[2][8][4];
    #pragma unroll
    for (int mt = 0; mt < 2; mt++)
        #pragma unroll
        for (int nt = 0; nt < 8; nt++)
            #pragma unroll
            for (int q = 0; q < 4; q++) c[mt][nt][q] = 0.f;

    int nK = Kp >> 3;

    #define ISSUE(kt, slot) do { \
        const uint2* _Ap = Ag + (kt) * 8; \
        const uint2* _Wp = Wg + (kt) * 8; \
        _Pragma("unroll") \
        for (int i = 0; i < 4; i++) { \
            unsigned off = (unsigned)((((slot) * 4 + i) * S4 + ar) * 16 + half * 8); \
            cp8(aSm + off, _Ap + i, aok); \
            cp8(wSm + off, _Wp + i, wok); \
        } \
    } while (0)

    #pragma unroll
    for (int s = 0; s < STAGES - 1; s++) {
        if (s < nK) ISSUE(s, s);
        asm volatile("cp.async.commit_group;");
    }

    for (int kt = 0; kt < nK; kt++) {
        asm volatile("cp.async.wait_group %0;" :: "n"(STAGES - 2));
        __syncthreads();

        int slot = kt & 3;
        const uint4* Ab = As + slot * 4 * S4;
        const uint4* Wb = Ws + slot * 4 * S4;

        uint4 fa[2][2];
        #pragma unroll
        for (int mt = 0; mt < 2; mt++) {
            int m0 = wm * 32 + mt * 16;
            fa[mt][0] = Ab[tig * S4 + m0 + g];
            fa[mt][1] = Ab[tig * S4 + m0 + g + 8];
        }
        unsigned ahi[2][4], alo[2][4];
        #pragma unroll
        for (int mt = 0; mt < 2; mt++) {
            ahi[mt][0] = fa[mt][0].x; ahi[mt][1] = fa[mt][1].x;
            ahi[mt][2] = fa[mt][0].z; ahi[mt][3] = fa[mt][1].z;
            alo[mt][0] = fa[mt][0].y; alo[mt][1] = fa[mt][1].y;
            alo[mt][2] = fa[mt][0].w; alo[mt][3] = fa[mt][1].w;
        }
        #pragma unroll
        for (int nt = 0; nt < 8; nt++) {
            int n0 = wn * 64 + nt * 8;
            uint4 fb = Wb[tig * S4 + n0 + g];
            unsigned bhi[2] = {fb.x, fb.z};
            unsigned blo[2] = {fb.y, fb.w};
            #pragma unroll
            for (int mt = 0; mt < 2; mt++) {
                mma16(c[mt][nt], alo[mt], bhi);
                mma16(c[mt][nt], ahi[mt], blo);
                mma16(c[mt][nt], ahi[mt], bhi);
            }
        }

        int pre = kt + STAGES - 1;
        if (pre < nK) ISSUE(pre, pre & 3);
        asm volatile("cp.async.commit_group;");
    }
    asm volatile("cp.async.wait_all;");

    #pragma unroll
    for (int mt = 0; mt < 2; mt++) {
        #pragma unroll
        for (int nt = 0; nt < 8; nt++) {
            int cc = col0 + wn * 64 + nt * 8 + 2 * tig;
            if (cc >= N) continue;
            #pragma unroll
            for (int hf = 0; hf < 2; hf++) {
                int r = row0 + wm * 32 + mt * 16 + g + hf * 8;
                if (r >= M) continue;
                float v0 = c[mt][nt][hf * 2 + 0];
                float v1 = c[mt][nt][hf * 2 + 1];
                long long ci = (long long)r * N + cc;
                if (op == 0) {
                    *(float2*)&C[ci] = make_float2(v0, v1);
                } else if (op == 1) {
                    float2 o = *(float2*)&C[ci];
                    o.x += v0; o.y += v1;
                    *(float2*)&C[ci] = o;
                    if (Caux) Caux[ci >> 1] = split_bf16_pair(o.x, o.y);
                } else if (op == 2) {
                    v0 += bias[cc]; v1 += bias[cc + 1];
                    *(float2*)&C[ci] = make_float2(v0 > 0.f ? v0 : 0.f, v1 > 0.f ? v1 : 0.f);
                } else {
                    v0 += bias[cc]; v1 += bias[cc + 1];
                    *(float2*)&C[ci] = make_float2(tanhf(v0), tanhf(v1));
                }
            }
        }
    }
    #undef ISSUE
}

// ---------------- prep: build 3 branch inputs ----------------
__global__ void k_prep(const float* __restrict__ hb, float* __restrict__ hcur) {
    long long i = (long long)blockIdx.x * 256 + threadIdx.x;
    if (i >= (long long)L_TOK * DM) return;
    int t = (int)(i >> 9);
    int d = (int)(i & 511);
    float v = hb[i];
    hcur[(long long)t * DM + d] = v;
    hcur[(long long)LP * DM + (long long)t * DM + (DM - 1 - d)] = v;
    int tt = (t % 100) * 100 + t / 100;
    hcur[2LL * LP * DM + (long long)tt * DM + d] = v;
}

__global__ void k_zeropad(float* __restrict__ hcur) {
    int i = blockIdx.x * 256 + threadIdx.x;
    const int tot = NB * (LP - L_TOK) * DM;
    if (i >= tot) return;
    int b = i / ((LP - L_TOK) * DM);
    int r = i % ((LP - L_TOK) * DM);
    hcur[(long long)b * LP * DM + (long long)L_TOK * DM + r] = 0.f;
}

// ---------------- depthwise causal conv + silu + split ----------------
__global__ void k_conv(const float* __restrict__ cw, const float* __restrict__ cb, int j) {
    int t = blockIdx.x, b = blockIdx.y;
    int lidx = 2 * b + j;
    const float* base = g_zx + (long long)b * LP * DPROJ + DI;
    long long tb = (long long)b * LP + t;
    for (int c = threadIdx.x; c < DXBC; c += blockDim.x) {
        float accv = cb[lidx * DXBC + c];
        #pragma unroll
        for (int k = 0; k < 4; k++) {
            int ttk = t - 3 + k;
            if (ttk >= 0)
                accv += base[(long long)ttk * DPROJ + c] * cw[(lidx * DXBC + c) * 4 + k];
        }
        float v = accv / (1.f + __expf(-accv));
        if (t >= L_TOK) v = 0.f;
        if (c < DI)            g_xs[tb * DI + c] = v;
        else if (c < DI + DS)  g_Bm[tb * DS + (c - DI)] = v;
        else                   g_Cm[tb * DS + (c - DI - DS)] = v;
    }
}

// ---------------- dt = softplus(dt_raw + bias), a = dt * A ----------------
__global__ void k_dt(const float* __restrict__ dt_bias, const float* __restrict__ A_log, int j) {
    long long idx = (long long)blockIdx.x * 256 + threadIdx.x;
    if (idx >= (long long)NB * LP * NH) return;
    int hd = (int)(idx % NH);
    int t  = (int)((idx / NH) % LP);
    int b  = (int)(idx / ((long long)NH * LP));
    int lidx = 2 * b + j;
    float draw = g_zx[((long long)b * LP + t) * DPROJ + DI + DXBC + hd];
    float xv = draw + dt_bias[lidx * NH + hd];
    float sp = (xv > 20.f) ? xv : log1pf(expf(xv));
    if (t >= L_TOK) sp = 0.f;
    float Ah = -expf(A_log[lidx * NH + hd]);
    g_dtv[((long long)b * LP + t) * NH + hd] = sp;
    g_av[((long long)(b * NH + hd)) * LP + t] = sp * Ah;
}

// ---------------- per-chunk inclusive cumsum of a ----------------
__global__ void k_cumsum() {
    int c = blockIdx.x, h = blockIdx.y, b = blockIdx.z;
    long long base = (long long)(b * NH + h) * LP + (long long)c * Q;
    int t = threadIdx.x;
    float x = g_av[base + t];
    #pragma unroll
    for (int o = 1; o < 32; o <<= 1) {
        float yv = __shfl_up_sync(0xffffffffu, x, o);
        if ((t & 31) >= o) x += yv;
    }
    __shared__ float w0;
    if (t == 31) w0 = x;
    __syncthreads();
    if (t >= 32) x += w0;
    g_cum[base + t] = x;
}

// ---------------- intra-chunk: tensor-core version ----------------
// per block (c,h,b): P = mask.exp (C B^T); Y = P U; S = (Bw)^T U
// smem tiles in tgemm uint4 {pair k, pair k+4} layout; sB aliased by split-P for stage 2.
#define SMEM_INTRA_MMA (4096 * 16 + 512)
__global__ __launch_bounds__(256) void k_intra_mma() {
    extern __shared__ uint4 smu[];
    uint4* sC  = smu;            // C  [t][k=n]
    uint4* sB  = smu + 1024;     // B  [s][k=n]  (aliased by split-P [t][k=s] in stage 2)
    uint4* sUT = smu + 2048;     // U^T[p][k=s]
    uint4* sBw = smu + 3072;     // Bw^T[n][k=s]
    float* scum = (float*)(smu + 4096);
    float* sdt  = scum + 64;

    int c = blockIdx.x, h = blockIdx.y, b = blockIdx.z;
    long long rowb = (long long)b * LP + (long long)c * Q;
    int tid = threadIdx.x;

    if (tid < 64) {
        scum[tid] = g_cum[(long long)(b * NH + h) * LP + (long long)c * Q + tid];
        sdt[tid]  = g_dtv[(rowb + tid) * NH + h];
    }
    __syncthreads();
    float T = scum[63];

    for (int i = tid; i < 1024; i += 256) {
        int slot = i >> 6, row = i & 63;
        int ks = slot >> 2, tg = slot & 3;
        int k0 = ks * 16 + tg * 2;
        long long rb = rowb + row;
        // C
        float2 c0 = *(const float2*)&g_Cm[rb * DS + k0];
        float2 c1 = *(const float2*)&g_Cm[rb * DS + k0 + 8];
        uint2 ch0 = split_bf16_pair(c0.x, c0.y);
        uint2 ch1 = split_bf16_pair(c1.x, c1.y);
        sC[i] = make_uint4(ch0.x, ch0.y, ch1.x, ch1.y);
        // B
        float2 b0 = *(const float2*)&g_Bm[rb * DS + k0];
        float2 b1 = *(const float2*)&g_Bm[rb * DS + k0 + 8];
        uint2 bh0 = split_bf16_pair(b0.x, b0.y);
        uint2 bh1 = split_bf16_pair(b1.x, b1.y);
        sB[i] = make_uint4(bh0.x, bh0.y, bh1.x, bh1.y);
        // U^T (row = p, k = s)
        float u0 = sdt[k0]     * g_xs[(rowb + k0)     * DI + h * HD + row];
        float u1 = sdt[k0 + 1] * g_xs[(rowb + k0 + 1) * DI + h * HD + row];
        float u2 = sdt[k0 + 8] * g_xs[(rowb + k0 + 8) * DI + h * HD + row];
        float u3 = sdt[k0 + 9] * g_xs[(rowb + k0 + 9) * DI + h * HD + row];
        uint2 uh0 = split_bf16_pair(u0, u1);
        uint2 uh1 = split_bf16_pair(u2, u3);
        sUT[i] = make_uint4(uh0.x, uh0.y, uh1.x, uh1.y);
        // Bw^T (row = n, k = s), weight exp(T - cum[s])
        float bw0 = g_Bm[(rowb + k0)     * DS + row] * __expf(T - scum[k0]);
        float bw1 = g_Bm[(rowb + k0 + 1) * DS + row] * __expf(T - scum[k0 + 1]);
        float bw2 = g_Bm[(rowb + k0 + 8) * DS + row] * __expf(T - scum[k0 + 8]);
        float bw3 = g_Bm[(rowb + k0 + 9) * DS + row] * __expf(T - scum[k0 + 9]);
        uint2 wh0 = split_bf16_pair(bw0, bw1);
        uint2 wh1 = split_bf16_pair(bw2, bw3);
        sBw[i] = make_uint4(wh0.x, wh0.y, wh1.x, wh1.y);
    }
    __syncthreads();

    int warp = tid >> 5, lane = tid & 31;
    int g = lane >> 2, tig = lane & 3;
    int r0 = (warp & 3) * 16, cbn = (warp >> 2) * 32;

    // stage 1: P_raw = C @ B^T
    float accP[4][4];
    #pragma unroll
    for (int nt = 0; nt < 4; nt++)
        #pragma unroll
        for (int q = 0; q < 4; q++) accP[nt][q] = 0.f;
    #pragma unroll
    for (int ks = 0; ks < 4; ks++) {
        uint4 fa0 = sC[(ks * 4 + tig) * 64 + r0 + g];
        uint4 fa1 = sC[(ks * 4 + tig) * 64 + r0 + g + 8];
        unsigned ahi[4] = {fa0.x, fa1.x, fa0.z, fa1.z};
        unsigned alo[4] = {fa0.y, fa1.y, fa0.w, fa1.w};
        #pragma unroll
        for (int nt = 0; nt < 4; nt++) {
            uint4 fb = sB[(ks * 4 + tig) * 64 + cbn + nt * 8 + g];
            unsigned bhi[2] = {fb.x, fb.z}, blo[2] = {fb.y, fb.w};
            mma16(accP[nt], alo, bhi);
            mma16(accP[nt], ahi, blo);
            mma16(accP[nt], ahi, bhi);
        }
    }
    __syncthreads();   // all warps done reading sB before aliasing

    // mask + exp, write split P into sB region
    uint2* sP2 = (uint2*)sB;
    #pragma unroll
    for (int nt = 0; nt < 4; nt++) {
        int scol = cbn + nt * 8 + 2 * tig;
        int Pp = scol >> 1;
        int ksp = Pp >> 3, tslot = Pp & 3, halfp = (Pp >> 2) & 1;
        #pragma unroll
        for (int hf = 0; hf < 2; hf++) {
            int t = r0 + g + hf * 8;
            float v0 = accP[nt][hf * 2], v1 = accP[nt][hf * 2 + 1];
            v0 = (scol     <= t) ? v0 * __expf(scum[t] - scum[scol])     : 0.f;
            v1 = (scol + 1 <= t) ? v1 * __expf(scum[t] - scum[scol + 1]) : 0.f;
            sP2[((ksp * 4 + tslot) * 64 + t) * 2 + halfp] = split_bf16_pair(v0, v1);
        }
    }
    __syncthreads();

    // stage 2: Y = P @ U (rows t), S = Bw^T @ U (rows n); share U^T fragments
    float accY[4][4], accS[4][4];
    #pragma unroll
    for (int nt = 0; nt < 4; nt++)
        #pragma unroll
        for (int q = 0; q < 4; q++) { accY[nt][q] = 0.f; accS[nt][q] = 0.f; }
    uint4* sP = sB;
    #pragma unroll
    for (int ks = 0; ks < 4; ks++) {
        uint4 fp0 = sP[(ks * 4 + tig) * 64 + r0 + g];
        uint4 fp1 = sP[(ks * 4 + tig) * 64 + r0 + g + 8];
        unsigned phi[4] = {fp0.x, fp1.x, fp0.z, fp1.z};
        unsigned plo[4] = {fp0.y, fp1.y, fp0.w, fp1.w};
        uint4 fw0 = sBw[(ks * 4 + tig) * 64 + r0 + g];
        uint4 fw1 = sBw[(ks * 4 + tig) * 64 + r0 + g + 8];
        unsigned whi[4] = {fw0.x, fw1.x, fw0.z, fw1.z};
        unsigned wlo[4] = {fw0.y, fw1.y, fw0.w, fw1.w};
        #pragma unroll
        for (int nt = 0; nt < 4; nt++) {
            uint4 fb = sUT[(ks * 4 + tig) * 64 + cbn + nt * 8 + g];
            unsigned bhi[2] = {fb.x, fb.z}, blo[2] = {fb.y, fb.w};
            mma16(accY[nt], plo, bhi); mma16(accY[nt], phi, blo); mma16(accY[nt], phi, bhi);
            mma16(accS[nt], wlo, bhi); mma16(accS[nt], whi, blo); mma16(accS[nt], whi, bhi);
        }
    }

    long long sbase = ((long long)(b * NH + h) * NC + c) * 4096;
    #pragma unroll
    for (int nt = 0; nt < 4; nt++) {
        int p = cbn + nt * 8 + 2 * tig;
        #pragma unroll
        for (int hf = 0; hf < 2; hf++) {
            int r = r0 + g + hf * 8;
            *(float2*)&g_y[(rowb + r) * DI + h * HD + p] =
                make_float2(accY[nt][hf * 2], accY[nt][hf * 2 + 1]);
            *(float2*)&g_schunk[sbase + r * 64 + p] =
                make_float2(accS[nt][hf * 2], accS[nt][hf * 2 + 1]);
        }
    }
}

// ---------------- sequential chunk-state recurrence ----------------
__global__ __launch_bounds__(256) void k_rec() {
    int bh = blockIdx.x;
    int tid = threadIdx.x;
    float S[16];
    #pragma unroll
    for (int i = 0; i < 16; i++) S[i] = 0.f;
    const float* cumrow = g_cum + (long long)bh * LP;
    for (int c = 0; c < NC; c++) {
        long long base = ((long long)bh * NC + c) * 4096;
        float e = __expf(cumrow[c * Q + 63]);
        #pragma unroll
        for (int i = 0; i < 16; i++) {
            int idx = tid + i * 256;
            g_sbef[base + idx] = S[i];
            S[i] = e * S[i] + g_schunk[base + idx];
        }
    }
}

// ---------------- inter-chunk: tensor-core version ----------------
// Yinter[t][p] = exp(cum_t) * sum_n C[t][n] Sbef[n][p];  y += Yinter + dh*xs
__global__ __launch_bounds__(256) void k_inter_mma(const float* __restrict__ Dh, int j) {
    __shared__ uint4 sC[1024];    // C [t][k=n]
    __shared__ uint4 sST[1024];   // Sbef^T [p][k=n]
    __shared__ float scum[64];

    int c = blockIdx.x, h = blockIdx.y, b = blockIdx.z;
    long long rowb = (long long)b * LP + (long long)c * Q;
    long long sbase = ((long long)(b * NH + h) * NC + c) * 4096;
    int tid = threadIdx.x;

    if (tid < 64)
        scum[tid] = g_cum[(long long)(b * NH + h) * LP + (long long)c * Q + tid];

    for (int i = tid; i < 1024; i += 256) {
        int slot = i >> 6, row = i & 63;
        int ks = slot >> 2, tg = slot & 3;
        int k0 = ks * 16 + tg * 2;
        long long rb = rowb + row;
        float2 c0 = *(const float2*)&g_Cm[rb * DS + k0];
        float2 c1 = *(const float2*)&g_Cm[rb * DS + k0 + 8];
        uint2 ch0 = split_bf16_pair(c0.x, c0.y);
        uint2 ch1 = split_bf16_pair(c1.x, c1.y);
        sC[i] = make_uint4(ch0.x, ch0.y, ch1.x, ch1.y);
        // Sbef^T (row = p, k = n)
        float s0 = g_sbef[sbase + (k0)     * 64 + row];
        float s1 = g_sbef[sbase + (k0 + 1) * 64 + row];
        float s2 = g_sbef[sbase + (k0 + 8) * 64 + row];
        float s3 = g_sbef[sbase + (k0 + 9) * 64 + row];
        uint2 sh0 = split_bf16_pair(s0, s1);
        uint2 sh1 = split_bf16_pair(s2, s3);
        sST[i] = make_uint4(sh0.x, sh0.y, sh1.x, sh1.y);
    }
    __syncthreads();

    int warp = tid >> 5, lane = tid & 31;
    int g = lane >> 2, tig = lane & 3;
    int r0 = (warp & 3) * 16, cbn = (warp >> 2) * 32;

    float acc[4][4];
    #pragma unroll
    for (int nt = 0; nt < 4; nt++)
        #pragma unroll
        for (int q = 0; q < 4; q++) acc[nt][q] = 0.f;
    #pragma unroll
    for (int ks = 0; ks < 4; ks++) {
        uint4 fa0 = sC[(ks * 4 + tig) * 64 + r0 + g];
        uint4 fa1 = sC[(ks * 4 + tig) * 64 + r0 + g + 8];
        unsigned ahi[4] = {fa0.x, fa1.x, fa0.z, fa1.z};
        unsigned alo[4] = {fa0.y, fa1.y, fa0.w, fa1.w};
        #pragma unroll
        for (int nt = 0; nt < 4; nt++) {
            uint4 fb = sST[(ks * 4 + tig) * 64 + cbn + nt * 8 + g];
            unsigned bhi[2] = {fb.x, fb.z}, blo[2] = {fb.y, fb.w};
            mma16(acc[nt], alo, bhi);
            mma16(acc[nt], ahi, blo);
            mma16(acc[nt], ahi, bhi);
        }
    }

    float dh = Dh[(2 * b + j) * NH + h];
    #pragma unroll
    for (int nt = 0; nt < 4; nt++) {
        int p = cbn + nt * 8 + 2 * tig;
        #pragma unroll
        for (int hf = 0; hf < 2; hf++) {
            int t = r0 + g + hf * 8;
            float e = __expf(scum[t]);
            long long ydx = (rowb + t) * DI + h * HD + p;
            float2 o = *(float2*)&g_y[ydx];
            float2 xs2 = *(const float2*)&g_xs[ydx];
            o.x += e * acc[nt][hf * 2]     + dh * xs2.x;
            o.y += e * acc[nt][hf * 2 + 1] + dh * xs2.y;
            *(float2*)&g_y[ydx] = o;
        }
    }
}

// ---------------- gate (silu(z)) + RMSNorm, writes split pairs directly ----------------
__global__ __launch_bounds__(256) void k_gate(const float* __restrict__ norm_w, int j) {
    int t = blockIdx.x, b = blockIdx.y;
    int lidx = 2 * b + j;
    const float* z = g_zx + ((long long)b * LP + t) * DPROJ;
    const float* yr = g_y + ((long long)b * LP + t) * DI;
    uint2* yo = g_ySp + ((long long)b * LP + t) * 512;
    int c0 = threadIdx.x * 4;
    float4 zv4 = *(const float4*)&z[c0];
    float4 yv4 = *(const float4*)&yr[c0];
    float vals[4];
    float zv[4] = {zv4.x, zv4.y, zv4.z, zv4.w};
    float yv[4] = {yv4.x, yv4.y, yv4.z, yv4.w};
    float ss = 0.f;
    #pragma unroll
    for (int i = 0; i < 4; i++) {
        float gv = yv[i] * (zv[i] / (1.f + __expf(-zv[i])));
        vals[i] = gv;
        ss += gv * gv;
    }
    float tot = bsum(ss);
    float scale = rsqrtf(tot / (float)DI + 1e-5f);
    float4 nw4 = *(const float4*)&norm_w[lidx * DI + c0];
    float nw[4] = {nw4.x, nw4.y, nw4.z, nw4.w};
    #pragma unroll
    for (int p = 0; p < 2; p++) {
        float v0 = vals[2 * p]     * scale * nw[2 * p];
        float v1 = vals[2 * p + 1] * scale * nw[2 * p + 1];
        yo[(c0 >> 1) + p] = split_bf16_pair(v0, v1);
    }
}

// ---------------- final LayerNorm: writes fp32 hn + split pairs ----------------
__global__ __launch_bounds__(256) void k_ln(const float* __restrict__ lnw, const float* __restrict__ lnb) {
    int g = blockIdx.x;
    int b = g / L_TOK, t = g % L_TOK;
    const float* row = g_hcur + ((long long)b * LP + t) * DM;
    int tid = threadIdx.x;
    float2 v = *(const float2*)&row[2 * tid];
    float s = bsum(v.x + v.y);
    float sq = bsum(v.x * v.x + v.y * v.y);
    float mu = s / (float)DM;
    float var = sq / (float)DM - mu * mu;
    float inv = rsqrtf(var + 1e-5f);
    float o0 = (v.x - mu) * inv * lnw[2 * tid]     + lnb[2 * tid];
    float o1 = (v.y - mu) * inv * lnw[2 * tid + 1] + lnb[2 * tid + 1];
    *(float2*)&g_hn[(long long)g * DM + 2 * tid] = make_float2(o0, o1);
    g_hnS[(long long)g * 256 + tid] = split_bf16_pair(o0, o1);
}

// ---------------- attention scalar score ----------------
__global__ void k_score(const float* __restrict__ w2, const float* __restrict__ b2) {
    int g = blockIdx.x;
    int tid = threadIdx.x;
    float v = g_s1[(long long)g * 128 + tid] * w2[tid];
    v = bsum(v);
    if (tid == 0) g_scoreb[g] = v + b2[0];
}

// ---------------- softmax over 30000 scores ----------------
__global__ void k_softmax() {
    const int n = NB * L_TOK;
    __shared__ float red[32];
    __shared__ float s_max, s_sum;
    int tid = threadIdx.x;
    float m = -1e30f;
    for (int i = tid; i < n; i += 1024) m = fmaxf(m, g_scoreb[i]);
    #pragma unroll
    for (int o = 16; o > 0; o >>= 1) m = fmaxf(m, __shfl_xor_sync(0xffffffffu, m, o));
    if ((tid & 31) == 0) red[tid >> 5] = m;
    __syncthreads();
    if (tid < 32) {
        float v = red[tid];
        #pragma unroll
        for (int o = 16; o > 0; o >>= 1) v = fmaxf(v, __shfl_xor_sync(0xffffffffu, v, o));
        if (tid == 0) s_max = v;
    }
    __syncthreads();
    float m0 = s_max;
    float s = 0.f;
    for (int i = tid; i < n; i += 1024) s += expf(g_scoreb[i] - m0);
    #pragma unroll
    for (int o = 16; o > 0; o >>= 1) s += __shfl_xor_sync(0xffffffffu, s, o);
    if ((tid & 31) == 0) red[tid >> 5] = s;
    __syncthreads();
    if (tid < 32) {
        float v = red[tid];
        #pragma unroll
        for (int o = 16; o > 0; o >>= 1) v += __shfl_xor_sync(0xffffffffu, v, o);
        if (tid == 0) s_sum = v;
    }
    __syncthreads();
    float inv = 1.f / s_sum;
    for (int i = tid; i < n; i += 1024) g_wts[i] = expf(g_scoreb[i] - m0) * inv;
}

// ---------------- pooled[d] = sum_g w[g]*hn[g][d] ----------------
__global__ __launch_bounds__(256) void k_pooled() {
    int d = blockIdx.x;
    float acc = 0.f;
    for (int g = threadIdx.x; g < NB * L_TOK; g += 256)
        acc += g_wts[g] * g_hn[(long long)g * DM + d];
    acc = bsum(acc);
    if (threadIdx.x == 0) g_pooled[d] = acc;
}

// ---------------- final classifier + softmax ----------------
__global__ void k_final(const float* __restrict__ cls_w, const float* __restrict__ cls_b,
                        float* __restrict__ out, int out_size) {
    int tid = threadIdx.x;
    int cls = tid >> 5, lane = tid & 31;
    float acc = 0.f;
    for (int d = lane; d < DM; d += 32) acc += g_pooled[d] * cls_w[cls * DM + d];
    #pragma unroll
    for (int o = 16; o > 0; o >>= 1) acc += __shfl_xor_sync(0xffffffffu, acc, o);
    __shared__ float lg[2];
    if (lane == 0) lg[cls] = acc;
    __syncthreads();
    if (tid == 0) {
        float l0 = lg[0] + cls_b[0], l1 = lg[1] + cls_b[1];
        float m = fmaxf(l0, l1);
        float e0 = expf(l0 - m), e1 = expf(l1 - m);
        float s = e0 + e1;
        out[0] = l0;
        out[1] = l1;
        if (out_size >= 4) { out[2] = e0 / s; out[3] = e1 / s; }
    }
}

// ---------------- launch ----------------
static inline void launch_split(const float* src, void* dst, long long npairs) {
    k_split<<<(int)((npairs + 255) / 256), 256>>>(src, (uint2*)dst, npairs);
}

extern "C" void kernel_launch(void* const* d_in, const int* in_sizes, int n_in,
                              void* d_out, int out_size) {
    const float* x        = (const float*)d_in[0];
    const float* fc1_w    = (const float*)d_in[1];
    const float* fc1_b    = (const float*)d_in[2];
    const float* in_proj_w= (const float*)d_in[3];
    const float* conv_w   = (const float*)d_in[4];
    const float* conv_b   = (const float*)d_in[5];
    const float* dt_bias  = (const float*)d_in[6];
    const float* A_log    = (const float*)d_in[7];
    const float* Dh       = (const float*)d_in[8];
    const float* norm_w   = (const float*)d_in[9];
    const float* out_proj_w=(const float*)d_in[10];
    const float* ln_w     = (const float*)d_in[11];
    const float* ln_b     = (const float*)d_in[12];
    const float* attn_w1  = (const float*)d_in[13];
    const float* attn_b1  = (const float*)d_in[14];
    const float* attn_w2  = (const float*)d_in[15];
    const float* attn_b2  = (const float*)d_in[16];
    const float* cls_w    = (const float*)d_in[17];
    const float* cls_b    = (const float*)d_in[18];
    float* out = (float*)d_out;

    void *p_hbase, *p_hcur, *p_zx, *p_y, *p_hn, *p_s1;
    void *p_xS, *p_fc1wS, *p_ipwS, *p_opwS, *p_aw1S, *p_hcurS, *p_ySp, *p_hnS;
    cudaGetSymbolAddress(&p_hbase, g_hbase);
    cudaGetSymbolAddress(&p_hcur,  g_hcur);
    cudaGetSymbolAddress(&p_zx,    g_zx);
    cudaGetSymbolAddress(&p_y,     g_y);
    cudaGetSymbolAddress(&p_hn,    g_hn);
    cudaGetSymbolAddress(&p_s1,    g_s1);
    cudaGetSymbolAddress(&p_xS,    g_xS);
    cudaGetSymbolAddress(&p_fc1wS, g_fc1wS);
    cudaGetSymbolAddress(&p_ipwS,  g_ipwS);
    cudaGetSymbolAddress(&p_opwS,  g_opwS);
    cudaGetSymbolAddress(&p_aw1S,  g_aw1S);
    cudaGetSymbolAddress(&p_hcurS, g_hcurS);
    cudaGetSymbolAddress(&p_ySp,   g_ySp);
    cudaGetSymbolAddress(&p_hnS,   g_hnS);

    cudaFuncSetAttribute(tgemm, cudaFuncAttributeMaxDynamicSharedMemorySize, TG_SMEM);
    cudaFuncSetAttribute(k_intra_mma, cudaFuncAttributeMaxDynamicSharedMemorySize, SMEM_INTRA_MMA);

    // weight + input conversions
    launch_split(x,         p_xS,    (long long)L_TOK * 512);
    launch_split(fc1_w,     p_fc1wS, (long long)DM * 512);
    launch_split(in_proj_w, p_ipwS,  (long long)6 * DPROJ * 256);
    launch_split(out_proj_w,p_opwS,  (long long)6 * DM * 512);
    launch_split(attn_w1,   p_aw1S,  (long long)128 * 256);

    // fc1: h = relu(x @ fc1_w^T + b)
    {
        dim3 grid((DM + 127) / 128, (L_TOK + 127) / 128, 1);
        tgemm<<<grid, 256, TG_SMEM>>>((const uint2*)p_xS, 0, (const uint2*)p_fc1wS, 0, fc1_b,
                                      (float*)p_hbase, 0, nullptr, L_TOK, DM, 512, 2, 0);
    }
    k_prep<<<(int)(((long long)L_TOK * DM + 255) / 256), 256>>>((const float*)p_hbase, (float*)p_hcur);
    k_zeropad<<<(NB * (LP - L_TOK) * DM + 255) / 256, 256>>>((float*)p_hcur);
    launch_split((const float*)p_hcur, p_hcurS, (long long)NB * LP * 256);

    for (int j = 0; j < 2; j++) {
        // in_proj
        {
            dim3 g1((DPROJ + 127) / 128, (LP + 127) / 128, NB);
            tgemm<<<g1, 256, TG_SMEM>>>((const uint2*)p_hcurS, (long long)LP * 256,
                                        (const uint2*)p_ipwS, (long long)DPROJ * 256, nullptr,
                                        (float*)p_zx, (long long)LP * DPROJ, nullptr,
                                        LP, DPROJ, 256, 0, j);
        }
        k_conv<<<dim3(LP, NB), 128>>>(conv_w, conv_b, j);
        k_dt<<<(int)(((long long)NB * LP * NH + 255) / 256), 256>>>(dt_bias, A_log, j);
        k_cumsum<<<dim3(NC, NH, NB), 64>>>();
        k_intra_mma<<<dim3(NC, NH, NB), 256, SMEM_INTRA_MMA>>>();
        k_rec<<<NB * NH, 256>>>();
        k_inter_mma<<<dim3(NC, NH, NB), 256>>>(Dh, j);
        k_gate<<<dim3(LP, NB), 256>>>(norm_w, j);
        // out_proj + residual accumulate (+ fused split of updated hcur for next layer)
        {
            dim3 g2((DM + 127) / 128, (LP + 127) / 128, NB);
            tgemm<<<g2, 256, TG_SMEM>>>((const uint2*)p_ySp, (long long)LP * 512,
                                        (const uint2*)p_opwS, (long long)DM * 512, nullptr,
                                        (float*)p_hcur, (long long)LP * DM,
                                        (j == 0) ? (uint2*)p_hcurS : nullptr,
                                        LP, DM, 512, 1, j);
        }
    }

    // final head
    k_ln<<<NB * L_TOK, 256>>>(ln_w, ln_b);
    {
        dim3 ga(1, (NB * L_TOK + 127) / 128, 1);
        tgemm<<<ga, 256, TG_SMEM>>>((const uint2*)p_hnS, 0, (const uint2*)p_aw1S, 0, attn_b1,
                                    (float*)p_s1, 0, nullptr, NB * L_TOK, 128, 256, 3, 0);
    }
    k_score<<<NB * L_TOK, 128>>>(attn_w2, attn_b2);
    k_softmax<<<1, 1024>>>();
    k_pooled<<<DM, 256>>>();
    k_final<<<1, 64>>>(cls_w, cls_b, out, out_size);
}

// round 8
// speedup vs baseline: 1.1643x; 1.1044x over previous
#include <cuda_runtime.h>
#include <cuda_bf16.h>
#include <math.h>

// ---------------- problem constants ----------------
#define L_TOK 10000
#define LP    10048          // 157 * 64 (padded length)
#define NC    157            // chunks
#define Q     64             // chunk length
#define DM    512
#define DI    1024
#define DS    64
#define NH    16
#define HD    64
#define DXBC  1152
#define DPROJ 2192
#define NB    3              // branches

// ---------------- scratch (device globals, no allocation) ----------------
__device__ __align__(16) float g_hcur [(size_t)NB*LP*DM];
__device__ __align__(16) float g_zx   [(size_t)NB*LP*DPROJ];
__device__ __align__(16) float g_xs   [(size_t)NB*LP*DI];
__device__ __align__(16) float g_Bm   [(size_t)NB*LP*DS];
__device__ __align__(16) float g_Cm   [(size_t)NB*LP*DS];
__device__ __align__(16) float g_dtv  [(size_t)NB*LP*NH];
__device__ __align__(16) float g_cum  [(size_t)NB*NH*LP];
__device__ __align__(16) float g_y    [(size_t)NB*LP*DI];
__device__ __align__(16) float g_schunk[(size_t)NB*NH*NC*DS*HD];
__device__ __align__(16) float g_sbef  [(size_t)NB*NH*NC*DS*HD];
__device__ __align__(16) float g_hn   [(size_t)NB*L_TOK*DM];
__device__ __align__(16) float g_s1   [(size_t)NB*L_TOK*128];
__device__ float g_scoreb[NB*L_TOK];
__device__ float g_wts   [NB*L_TOK];
__device__ float g_pooled[DM];

// split-bf16 buffers (uint2 = {hi bf16x2, lo bf16x2} covering 2 consecutive k)
__device__ __align__(16) uint2 g_xS   [(size_t)L_TOK*512];
__device__ __align__(16) uint2 g_fc1wS[(size_t)DM*512];
__device__ __align__(16) uint2 g_ipwS [(size_t)6*DPROJ*256];
__device__ __align__(16) uint2 g_opwS [(size_t)6*DM*512];
__device__ __align__(16) uint2 g_aw1S [(size_t)128*256];
__device__ __align__(16) uint2 g_hcurS[(size_t)NB*LP*256];
__device__ __align__(16) uint2 g_ySp  [(size_t)NB*LP*512];
__device__ __align__(16) uint2 g_hnS  [(size_t)NB*L_TOK*256];

// ---------------- helpers ----------------
__device__ __forceinline__ float bsum(float v) {
    __shared__ float sh[32];
    int lane = threadIdx.x & 31, w = threadIdx.x >> 5;
    #pragma unroll
    for (int o = 16; o > 0; o >>= 1) v += __shfl_xor_sync(0xffffffffu, v, o);
    if (lane == 0) sh[w] = v;
    __syncthreads();
    int nw = blockDim.x >> 5;
    v = (threadIdx.x < nw) ? sh[threadIdx.x] : 0.f;
    if (w == 0) {
        #pragma unroll
        for (int o = 16; o > 0; o >>= 1) v += __shfl_xor_sync(0xffffffffu, v, o);
        if (threadIdx.x == 0) sh[0] = v;
    }
    __syncthreads();
    float r = sh[0];
    __syncthreads();
    return r;
}

// ---------------- bf16 split helpers ----------------
__device__ __forceinline__ uint2 split_bf16_pair(float f0, float f1) {
    unsigned hp, lp;
    asm("cvt.rn.bf16x2.f32 %0, %1, %2;" : "=r"(hp) : "f"(f1), "f"(f0));
    __nv_bfloat162 h = *reinterpret_cast<__nv_bfloat162*>(&hp);
    float r0 = f0 - __bfloat162float(h.x);
    float r1 = f1 - __bfloat162float(h.y);
    asm("cvt.rn.bf16x2.f32 %0, %1, %2;" : "=r"(lp) : "f"(r1), "f"(r0));
    uint2 q; q.x = hp; q.y = lp;
    return q;
}

__global__ void k_split(const float* __restrict__ in, uint2* __restrict__ out, long long npairs) {
    long long i = (long long)blockIdx.x * 256 + threadIdx.x;
    if (i >= npairs) return;
    float2 v = ((const float2*)in)[i];
    out[i] = split_bf16_pair(v.x, v.y);
}

__device__ __forceinline__ void mma16(float c[4], const unsigned a[4], const unsigned b[2]) {
    asm volatile(
        "mma.sync.aligned.m16n8k16.row.col.f32.bf16.bf16.f32 "
        "{%0,%1,%2,%3},{%4,%5,%6,%7},{%8,%9},{%0,%1,%2,%3};"
        : "+f"(c[0]), "+f"(c[1]), "+f"(c[2]), "+f"(c[3])
        : "r"(a[0]), "r"(a[1]), "r"(a[2]), "r"(a[3]), "r"(b[0]), "r"(b[1]));
}

__device__ __forceinline__ void cp8(unsigned dst, const void* src, bool pred) {
    int sz = pred ? 8 : 0;
    asm volatile("cp.async.ca.shared.global [%0], [%1], 8, %2;" :: "r"(dst), "l"(src), "r"(sz));
}

// ---------------- tensor-core GEMM, cp.async 4-stage pipeline ----------------
// op: 0=store, 1=C+= (opt split to Caux), 2=relu(v+bias), 3=tanh(v+bias),
//     4=fc1 fused: relu(v+bias) -> write 3 branch copies of hcur + hcurS splits
#define STAGES 4
#define S4 130
#define TG_SMEM (STAGES * 4 * S4 * 16 * 2)

__global__ __launch_bounds__(256, 2) void tgemm(
    const uint2* __restrict__ A, long long sA,
    const uint2* __restrict__ W, long long sW,
    const float* __restrict__ bias,
    float* __restrict__ C, long long sC,
    uint2* __restrict__ Caux,
    int M, int N, int Kp, int op, int joff)
{
    extern __shared__ uint4 sm4[];
    uint4* As = sm4;
    uint4* Ws = sm4 + STAGES * 4 * S4;

    int z = blockIdx.z;
    A += (long long)z * sA;
    C += (long long)z * sC;
    W += (long long)(2 * z + joff) * sW;
    if (Caux) Caux += (long long)z * (sC >> 1);

    int tid = threadIdx.x;
    int warp = tid >> 5, lane = tid & 31;
    int wm = warp & 3, wn = warp >> 2;
    int g = lane >> 2, tig = lane & 3;
    int row0 = blockIdx.y * 128, col0 = blockIdx.x * 128;

    int ar = tid >> 1, half = tid & 1;
    bool aok = (row0 + ar) < M;
    bool wok = (col0 + ar) < N;
    const uint2* Ag = A + (long long)(row0 + ar) * Kp + half * 4;
    const uint2* Wg = W + (long long)(col0 + ar) * Kp + half * 4;
    unsigned aSm = (unsigned)__cvta_generic_to_shared(As);
    unsigned wSm = (unsigned)__cvta_generic_to_shared(Ws);

    float c[2][8][4];
    #pragma unroll
    for (int mt = 0; mt < 2; mt++)
        #pragma unroll
        for (int nt = 0; nt < 8; nt++)
            #pragma unroll
            for (int q = 0; q < 4; q++) c[mt][nt][q] = 0.f;

    int nK = Kp >> 3;

    #define ISSUE(kt, slot) do { \
        const uint2* _Ap = Ag + (kt) * 8; \
        const uint2* _Wp = Wg + (kt) * 8; \
        _Pragma("unroll") \
        for (int i = 0; i < 4; i++) { \
            unsigned off = (unsigned)((((slot) * 4 + i) * S4 + ar) * 16 + half * 8); \
            cp8(aSm + off, _Ap + i, aok); \
            cp8(wSm + off, _Wp + i, wok); \
        } \
    } while (0)

    #pragma unroll
    for (int s = 0; s < STAGES - 1; s++) {
        if (s < nK) ISSUE(s, s);
        asm volatile("cp.async.commit_group;");
    }

    for (int kt = 0; kt < nK; kt++) {
        asm volatile("cp.async.wait_group %0;" :: "n"(STAGES - 2));
        __syncthreads();

        int slot = kt & 3;
        const uint4* Ab = As + slot * 4 * S4;
        const uint4* Wb = Ws + slot * 4 * S4;

        uint4 fa[2][2];
        #pragma unroll
        for (int mt = 0; mt < 2; mt++) {
            int m0 = wm * 32 + mt * 16;
            fa[mt][0] = Ab[tig * S4 + m0 + g];
            fa[mt][1] = Ab[tig * S4 + m0 + g + 8];
        }
        unsigned ahi[2][4], alo[2][4];
        #pragma unroll
        for (int mt = 0; mt < 2; mt++) {
            ahi[mt][0] = fa[mt][0].x; ahi[mt][1] = fa[mt][1].x;
            ahi[mt][2] = fa[mt][0].z; ahi[mt][3] = fa[mt][1].z;
            alo[mt][0] = fa[mt][0].y; alo[mt][1] = fa[mt][1].y;
            alo[mt][2] = fa[mt][0].w; alo[mt][3] = fa[mt][1].w;
        }
        #pragma unroll
        for (int nt = 0; nt < 8; nt++) {
            int n0 = wn * 64 + nt * 8;
            uint4 fb = Wb[tig * S4 + n0 + g];
            unsigned bhi[2] = {fb.x, fb.z};
            unsigned blo[2] = {fb.y, fb.w};
            #pragma unroll
            for (int mt = 0; mt < 2; mt++) {
                mma16(c[mt][nt], alo[mt], bhi);
                mma16(c[mt][nt], ahi[mt], blo);
                mma16(c[mt][nt], ahi[mt], bhi);
            }
        }

        int pre = kt + STAGES - 1;
        if (pre < nK) ISSUE(pre, pre & 3);
        asm volatile("cp.async.commit_group;");
    }
    asm volatile("cp.async.wait_all;");

    #pragma unroll
    for (int mt = 0; mt < 2; mt++) {
        #pragma unroll
        for (int nt = 0; nt < 8; nt++) {
            int cc = col0 + wn * 64 + nt * 8 + 2 * tig;
            if (cc >= N) continue;
            #pragma unroll
            for (int hf = 0; hf < 2; hf++) {
                int r = row0 + wm * 32 + mt * 16 + g + hf * 8;
                if (r >= M) continue;
                float v0 = c[mt][nt][hf * 2 + 0];
                float v1 = c[mt][nt][hf * 2 + 1];
                long long ci = (long long)r * N + cc;
                if (op == 0) {
                    *(float2*)&C[ci] = make_float2(v0, v1);
                } else if (op == 1) {
                    float2 o = *(float2*)&C[ci];
                    o.x += v0; o.y += v1;
                    *(float2*)&C[ci] = o;
                    if (Caux) Caux[ci >> 1] = split_bf16_pair(o.x, o.y);
                } else if (op == 2) {
                    v0 += bias[cc]; v1 += bias[cc + 1];
                    *(float2*)&C[ci] = make_float2(v0 > 0.f ? v0 : 0.f, v1 > 0.f ? v1 : 0.f);
                } else if (op == 3) {
                    v0 += bias[cc]; v1 += bias[cc + 1];
                    *(float2*)&C[ci] = make_float2(tanhf(v0), tanhf(v1));
                } else {
                    // op 4: fused fc1 + branch prep + splits
                    float v0r = fmaxf(v0 + bias[cc], 0.f);
                    float v1r = fmaxf(v1 + bias[cc + 1], 0.f);
                    long long t = r;
                    // branch 0
                    *(float2*)&g_hcur[t * DM + cc] = make_float2(v0r, v1r);
                    g_hcurS[t * 256 + (cc >> 1)] = split_bf16_pair(v0r, v1r);
                    // branch 1: feature flip
                    *(float2*)&g_hcur[(long long)LP * DM + t * DM + (510 - cc)] = make_float2(v1r, v0r);
                    g_hcurS[(long long)LP * 256 + t * 256 + (255 - (cc >> 1))] = split_bf16_pair(v1r, v0r);
                    // branch 2: grid transpose
                    int tt = ((int)t % 100) * 100 + (int)t / 100;
                    *(float2*)&g_hcur[2LL * LP * DM + (long long)tt * DM + cc] = make_float2(v0r, v1r);
                    g_hcurS[2LL * LP * 256 + (long long)tt * 256 + (cc >> 1)] = split_bf16_pair(v0r, v1r);
                }
            }
        }
    }
    #undef ISSUE
}

// ---------------- zero pad rows (fp32 + split) ----------------
__global__ void k_zeropad2() {
    int i = blockIdx.x * 256 + threadIdx.x;
    const int tot = NB * (LP - L_TOK) * DM;
    if (i >= tot) return;
    int b = i / ((LP - L_TOK) * DM);
    int rrem = i % ((LP - L_TOK) * DM);
    int t = L_TOK + rrem / DM;
    int d = rrem % DM;
    g_hcur[((long long)b * LP + t) * DM + d] = 0.f;
    if ((d & 1) == 0) g_hcurS[((long long)b * LP + t) * 256 + (d >> 1)] = make_uint2(0u, 0u);
}

// ---------------- fused conv + silu + dt + cumsum (per chunk, branch) ----------------
__global__ __launch_bounds__(256) void k_convfused(
    const float* __restrict__ cw, const float* __restrict__ cb,
    const float* __restrict__ dt_bias, const float* __restrict__ A_log, int j)
{
    __shared__ float av_s[NH * 64];
    int c = blockIdx.x, b = blockIdx.y;
    int lidx = 2 * b + j;
    int tid = threadIdx.x;
    const float* zbase = g_zx + (long long)b * LP * DPROJ;
    int gt0 = c * Q;

    for (int cc = tid; cc < DXBC; cc += 256) {
        const float* col = zbase + DI + cc;
        const float* wp = cw + (long long)(lidx * DXBC + cc) * 4;
        float w0 = wp[0], w1 = wp[1], w2 = wp[2], w3 = wp[3];
        float bia = cb[lidx * DXBC + cc];
        float h3 = (gt0 - 3 >= 0) ? col[(long long)(gt0 - 3) * DPROJ] : 0.f;
        float h2 = (gt0 - 2 >= 0) ? col[(long long)(gt0 - 2) * DPROJ] : 0.f;
        float h1 = (gt0 - 1 >= 0) ? col[(long long)(gt0 - 1) * DPROJ] : 0.f;
        for (int t = 0; t < Q; t++) {
            int gt = gt0 + t;
            float cur = col[(long long)gt * DPROJ];
            float a = bia + w0 * h3 + w1 * h2 + w2 * h1 + w3 * cur;
            float v = a / (1.f + __expf(-a));
            if (gt >= L_TOK) v = 0.f;
            long long tb = (long long)b * LP + gt;
            if (cc < DI)            g_xs[tb * DI + cc] = v;
            else if (cc < DI + DS)  g_Bm[tb * DS + (cc - DI)] = v;
            else                    g_Cm[tb * DS + (cc - DI - DS)] = v;
            h3 = h2; h2 = h1; h1 = cur;
        }
    }

    // dt softplus + a = dt*A (into smem)
    #pragma unroll
    for (int k = 0; k < 4; k++) {
        int idx = tid + k * 256;          // 0..1023
        int h = idx & 15, t = idx >> 4;
        int gt = gt0 + t;
        float draw = zbase[(long long)gt * DPROJ + DI + DXBC + h];
        float xv = draw + dt_bias[lidx * NH + h];
        float sp = (xv > 20.f) ? xv : log1pf(expf(xv));
        if (gt >= L_TOK) sp = 0.f;
        g_dtv[((long long)b * LP + gt) * NH + h] = sp;
        float Ah = -expf(A_log[lidx * NH + h]);
        av_s[h * 64 + t] = sp * Ah;
    }
    __syncthreads();

    // per-head inclusive cumsum over 64 (8 warps x 2 heads)
    int warp = tid >> 5, lane = tid & 31;
    #pragma unroll
    for (int hh = 0; hh < 2; hh++) {
        int h = warp * 2 + hh;
        float x1 = av_s[h * 64 + lane];
        float x2 = av_s[h * 64 + 32 + lane];
        #pragma unroll
        for (int o = 1; o < 32; o <<= 1) { float yv = __shfl_up_sync(0xffffffffu, x1, o); if (lane >= o) x1 += yv; }
        #pragma unroll
        for (int o = 1; o < 32; o <<= 1) { float yv = __shfl_up_sync(0xffffffffu, x2, o); if (lane >= o) x2 += yv; }
        float tot1 = __shfl_sync(0xffffffffu, x1, 31);
        x2 += tot1;
        long long base = (long long)(b * NH + h) * LP + (long long)c * Q;
        g_cum[base + lane] = x1;
        g_cum[base + 32 + lane] = x2;
    }
}

// ---------------- intra-chunk: tensor-core version ----------------
#define SMEM_INTRA_MMA (4096 * 16 + 512)
__global__ __launch_bounds__(256) void k_intra_mma() {
    extern __shared__ uint4 smu[];
    uint4* sC  = smu;
    uint4* sB  = smu + 1024;
    uint4* sUT = smu + 2048;
    uint4* sBw = smu + 3072;
    float* scum = (float*)(smu + 4096);
    float* sdt  = scum + 64;

    int c = blockIdx.x, h = blockIdx.y, b = blockIdx.z;
    long long rowb = (long long)b * LP + (long long)c * Q;
    int tid = threadIdx.x;

    if (tid < 64) {
        scum[tid] = g_cum[(long long)(b * NH + h) * LP + (long long)c * Q + tid];
        sdt[tid]  = g_dtv[(rowb + tid) * NH + h];
    }
    __syncthreads();
    float T = scum[63];

    for (int i = tid; i < 1024; i += 256) {
        int slot = i >> 6, row = i & 63;
        int ks = slot >> 2, tg = slot & 3;
        int k0 = ks * 16 + tg * 2;
        long long rb = rowb + row;
        float2 c0 = *(const float2*)&g_Cm[rb * DS + k0];
        float2 c1 = *(const float2*)&g_Cm[rb * DS + k0 + 8];
        uint2 ch0 = split_bf16_pair(c0.x, c0.y);
        uint2 ch1 = split_bf16_pair(c1.x, c1.y);
        sC[i] = make_uint4(ch0.x, ch0.y, ch1.x, ch1.y);
        float2 b0 = *(const float2*)&g_Bm[rb * DS + k0];
        float2 b1 = *(const float2*)&g_Bm[rb * DS + k0 + 8];
        uint2 bh0 = split_bf16_pair(b0.x, b0.y);
        uint2 bh1 = split_bf16_pair(b1.x, b1.y);
        sB[i] = make_uint4(bh0.x, bh0.y, bh1.x, bh1.y);
        float u0 = sdt[k0]     * g_xs[(rowb + k0)     * DI + h * HD + row];
        float u1 = sdt[k0 + 1] * g_xs[(rowb + k0 + 1) * DI + h * HD + row];
        float u2 = sdt[k0 + 8] * g_xs[(rowb + k0 + 8) * DI + h * HD + row];
        float u3 = sdt[k0 + 9] * g_xs[(rowb + k0 + 9) * DI + h * HD + row];
        uint2 uh0 = split_bf16_pair(u0, u1);
        uint2 uh1 = split_bf16_pair(u2, u3);
        sUT[i] = make_uint4(uh0.x, uh0.y, uh1.x, uh1.y);
        float bw0 = g_Bm[(rowb + k0)     * DS + row] * __expf(T - scum[k0]);
        float bw1 = g_Bm[(rowb + k0 + 1) * DS + row] * __expf(T - scum[k0 + 1]);
        float bw2 = g_Bm[(rowb + k0 + 8) * DS + row] * __expf(T - scum[k0 + 8]);
        float bw3 = g_Bm[(rowb + k0 + 9) * DS + row] * __expf(T - scum[k0 + 9]);
        uint2 wh0 = split_bf16_pair(bw0, bw1);
        uint2 wh1 = split_bf16_pair(bw2, bw3);
        sBw[i] = make_uint4(wh0.x, wh0.y, wh1.x, wh1.y);
    }
    __syncthreads();

    int warp = tid >> 5, lane = tid & 31;
    int g = lane >> 2, tig = lane & 3;
    int r0 = (warp & 3) * 16, cbn = (warp >> 2) * 32;

    float accP[4][4];
    #pragma unroll
    for (int nt = 0; nt < 4; nt++)
        #pragma unroll
        for (int q = 0; q < 4; q++) accP[nt][q] = 0.f;
    #pragma unroll
    for (int ks = 0; ks < 4; ks++) {
        uint4 fa0 = sC[(ks * 4 + tig) * 64 + r0 + g];
        uint4 fa1 = sC[(ks * 4 + tig) * 64 + r0 + g + 8];
        unsigned ahi[4] = {fa0.x, fa1.x, fa0.z, fa1.z};
        unsigned alo[4] = {fa0.y, fa1.y, fa0.w, fa1.w};
        #pragma unroll
        for (int nt = 0; nt < 4; nt++) {
            uint4 fb = sB[(ks * 4 + tig) * 64 + cbn + nt * 8 + g];
            unsigned bhi[2] = {fb.x, fb.z}, blo[2] = {fb.y, fb.w};
            mma16(accP[nt], alo, bhi);
            mma16(accP[nt], ahi, blo);
            mma16(accP[nt], ahi, bhi);
        }
    }
    __syncthreads();

    uint2* sP2 = (uint2*)sB;
    #pragma unroll
    for (int nt = 0; nt < 4; nt++) {
        int scol = cbn + nt * 8 + 2 * tig;
        int Pp = scol >> 1;
        int ksp = Pp >> 3, tslot = Pp & 3, halfp = (Pp >> 2) & 1;
        #pragma unroll
        for (int hf = 0; hf < 2; hf++) {
            int t = r0 + g + hf * 8;
            float v0 = accP[nt][hf * 2], v1 = accP[nt][hf * 2 + 1];
            v0 = (scol     <= t) ? v0 * __expf(scum[t] - scum[scol])     : 0.f;
            v1 = (scol + 1 <= t) ? v1 * __expf(scum[t] - scum[scol + 1]) : 0.f;
            sP2[((ksp * 4 + tslot) * 64 + t) * 2 + halfp] = split_bf16_pair(v0, v1);
        }
    }
    __syncthreads();

    float accY[4][4], accS[4][4];
    #pragma unroll
    for (int nt = 0; nt < 4; nt++)
        #pragma unroll
        for (int q = 0; q < 4; q++) { accY[nt][q] = 0.f; accS[nt][q] = 0.f; }
    uint4* sP = sB;
    #pragma unroll
    for (int ks = 0; ks < 4; ks++) {
        uint4 fp0 = sP[(ks * 4 + tig) * 64 + r0 + g];
        uint4 fp1 = sP[(ks * 4 + tig) * 64 + r0 + g + 8];
        unsigned phi[4] = {fp0.x, fp1.x, fp0.z, fp1.z};
        unsigned plo[4] = {fp0.y, fp1.y, fp0.w, fp1.w};
        uint4 fw0 = sBw[(ks * 4 + tig) * 64 + r0 + g];
        uint4 fw1 = sBw[(ks * 4 + tig) * 64 + r0 + g + 8];
        unsigned whi[4] = {fw0.x, fw1.x, fw0.z, fw1.z};
        unsigned wlo[4] = {fw0.y, fw1.y, fw0.w, fw1.w};
        #pragma unroll
        for (int nt = 0; nt < 4; nt++) {
            uint4 fb = sUT[(ks * 4 + tig) * 64 + cbn + nt * 8 + g];
            unsigned bhi[2] = {fb.x, fb.z}, blo[2] = {fb.y, fb.w};
            mma16(accY[nt], plo, bhi); mma16(accY[nt], phi, blo); mma16(accY[nt], phi, bhi);
            mma16(accS[nt], wlo, bhi); mma16(accS[nt], whi, blo); mma16(accS[nt], whi, bhi);
        }
    }

    long long sbase = ((long long)(b * NH + h) * NC + c) * 4096;
    #pragma unroll
    for (int nt = 0; nt < 4; nt++) {
        int p = cbn + nt * 8 + 2 * tig;
        #pragma unroll
        for (int hf = 0; hf < 2; hf++) {
            int r = r0 + g + hf * 8;
            *(float2*)&g_y[(rowb + r) * DI + h * HD + p] =
                make_float2(accY[nt][hf * 2], accY[nt][hf * 2 + 1]);
            *(float2*)&g_schunk[sbase + r * 64 + p] =
                make_float2(accS[nt][hf * 2], accS[nt][hf * 2 + 1]);
        }
    }
}

// ---------------- sequential chunk-state recurrence (4-way split) ----------------
__global__ __launch_bounds__(256) void k_rec() {
    int bh = blockIdx.x;        // 0..47
    int qd = blockIdx.y;        // 0..3
    int tid = threadIdx.x;
    int off = qd * 1024 + tid;
    float S[4];
    #pragma unroll
    for (int i = 0; i < 4; i++) S[i] = 0.f;
    const float* cumrow = g_cum + (long long)bh * LP;
    for (int c = 0; c < NC; c++) {
        long long base = ((long long)bh * NC + c) * 4096;
        float e = __expf(cumrow[c * Q + 63]);
        #pragma unroll
        for (int i = 0; i < 4; i++) {
            int idx = off + i * 256;
            g_sbef[base + idx] = S[i];
            S[i] = e * S[i] + g_schunk[base + idx];
        }
    }
}

// ---------------- inter-chunk: tensor-core version ----------------
__global__ __launch_bounds__(256) void k_inter_mma(const float* __restrict__ Dh, int j) {
    __shared__ uint4 sC[1024];
    __shared__ uint4 sST[1024];
    __shared__ float scum[64];

    int c = blockIdx.x, h = blockIdx.y, b = blockIdx.z;
    long long rowb = (long long)b * LP + (long long)c * Q;
    long long sbase = ((long long)(b * NH + h) * NC + c) * 4096;
    int tid = threadIdx.x;

    if (tid < 64)
        scum[tid] = g_cum[(long long)(b * NH + h) * LP + (long long)c * Q + tid];

    for (int i = tid; i < 1024; i += 256) {
        int slot = i >> 6, row = i & 63;
        int ks = slot >> 2, tg = slot & 3;
        int k0 = ks * 16 + tg * 2;
        long long rb = rowb + row;
        float2 c0 = *(const float2*)&g_Cm[rb * DS + k0];
        float2 c1 = *(const float2*)&g_Cm[rb * DS + k0 + 8];
        uint2 ch0 = split_bf16_pair(c0.x, c0.y);
        uint2 ch1 = split_bf16_pair(c1.x, c1.y);
        sC[i] = make_uint4(ch0.x, ch0.y, ch1.x, ch1.y);
        float s0 = g_sbef[sbase + (k0)     * 64 + row];
        float s1 = g_sbef[sbase + (k0 + 1) * 64 + row];
        float s2 = g_sbef[sbase + (k0 + 8) * 64 + row];
        float s3 = g_sbef[sbase + (k0 + 9) * 64 + row];
        uint2 sh0 = split_bf16_pair(s0, s1);
        uint2 sh1 = split_bf16_pair(s2, s3);
        sST[i] = make_uint4(sh0.x, sh0.y, sh1.x, sh1.y);
    }
    __syncthreads();

    int warp = tid >> 5, lane = tid & 31;
    int g = lane >> 2, tig = lane & 3;
    int r0 = (warp & 3) * 16, cbn = (warp >> 2) * 32;

    float acc[4][4];
    #pragma unroll
    for (int nt = 0; nt < 4; nt++)
        #pragma unroll
        for (int q = 0; q < 4; q++) acc[nt][q] = 0.f;
    #pragma unroll
    for (int ks = 0; ks < 4; ks++) {
        uint4 fa0 = sC[(ks * 4 + tig) * 64 + r0 + g];
        uint4 fa1 = sC[(ks * 4 + tig) * 64 + r0 + g + 8];
        unsigned ahi[4] = {fa0.x, fa1.x, fa0.z, fa1.z};
        unsigned alo[4] = {fa0.y, fa1.y, fa0.w, fa1.w};
        #pragma unroll
        for (int nt = 0; nt < 4; nt++) {
            uint4 fb = sST[(ks * 4 + tig) * 64 + cbn + nt * 8 + g];
            unsigned bhi[2] = {fb.x, fb.z}, blo[2] = {fb.y, fb.w};
            mma16(acc[nt], alo, bhi);
            mma16(acc[nt], ahi, blo);
            mma16(acc[nt], ahi, bhi);
        }
    }

    float dh = Dh[(2 * b + j) * NH + h];
    #pragma unroll
    for (int nt = 0; nt < 4; nt++) {
        int p = cbn + nt * 8 + 2 * tig;
        #pragma unroll
        for (int hf = 0; hf < 2; hf++) {
            int t = r0 + g + hf * 8;
            float e = __expf(scum[t]);
            long long ydx = (rowb + t) * DI + h * HD + p;
            float2 o = *(float2*)&g_y[ydx];
            float2 xs2 = *(const float2*)&g_xs[ydx];
            o.x += e * acc[nt][hf * 2]     + dh * xs2.x;
            o.y += e * acc[nt][hf * 2 + 1] + dh * xs2.y;
            *(float2*)&g_y[ydx] = o;
        }
    }
}

// ---------------- gate (silu(z)) + RMSNorm, writes split pairs directly ----------------
__global__ __launch_bounds__(256) void k_gate(const float* __restrict__ norm_w, int j) {
    int t = blockIdx.x, b = blockIdx.y;
    int lidx = 2 * b + j;
    const float* z = g_zx + ((long long)b * LP + t) * DPROJ;
    const float* yr = g_y + ((long long)b * LP + t) * DI;
    uint2* yo = g_ySp + ((long long)b * LP + t) * 512;
    int c0 = threadIdx.x * 4;
    float4 zv4 = *(const float4*)&z[c0];
    float4 yv4 = *(const float4*)&yr[c0];
    float vals[4];
    float zv[4] = {zv4.x, zv4.y, zv4.z, zv4.w};
    float yv[4] = {yv4.x, yv4.y, yv4.z, yv4.w};
    float ss = 0.f;
    #pragma unroll
    for (int i = 0; i < 4; i++) {
        float gv = yv[i] * (zv[i] / (1.f + __expf(-zv[i])));
        vals[i] = gv;
        ss += gv * gv;
    }
    float tot = bsum(ss);
    float scale = rsqrtf(tot / (float)DI + 1e-5f);
    float4 nw4 = *(const float4*)&norm_w[lidx * DI + c0];
    float nw[4] = {nw4.x, nw4.y, nw4.z, nw4.w};
    #pragma unroll
    for (int p = 0; p < 2; p++) {
        float v0 = vals[2 * p]     * scale * nw[2 * p];
        float v1 = vals[2 * p + 1] * scale * nw[2 * p + 1];
        yo[(c0 >> 1) + p] = split_bf16_pair(v0, v1);
    }
}

// ---------------- final LayerNorm: writes fp32 hn + split pairs ----------------
__global__ __launch_bounds__(256) void k_ln(const float* __restrict__ lnw, const float* __restrict__ lnb) {
    int g = blockIdx.x;
    int b = g / L_TOK, t = g % L_TOK;
    const float* row = g_hcur + ((long long)b * LP + t) * DM;
    int tid = threadIdx.x;
    float2 v = *(const float2*)&row[2 * tid];
    float s = bsum(v.x + v.y);
    float sq = bsum(v.x * v.x + v.y * v.y);
    float mu = s / (float)DM;
    float var = sq / (float)DM - mu * mu;
    float inv = rsqrtf(var + 1e-5f);
    float o0 = (v.x - mu) * inv * lnw[2 * tid]     + lnb[2 * tid];
    float o1 = (v.y - mu) * inv * lnw[2 * tid + 1] + lnb[2 * tid + 1];
    *(float2*)&g_hn[(long long)g * DM + 2 * tid] = make_float2(o0, o1);
    g_hnS[(long long)g * 256 + tid] = split_bf16_pair(o0, o1);
}

// ---------------- attention scalar score ----------------
__global__ void k_score(const float* __restrict__ w2, const float* __restrict__ b2) {
    int g = blockIdx.x;
    int tid = threadIdx.x;
    float v = g_s1[(long long)g * 128 + tid] * w2[tid];
    v = bsum(v);
    if (tid == 0) g_scoreb[g] = v + b2[0];
}

// ---------------- softmax over 30000 scores (+ zero pooled) ----------------
__global__ void k_softmax() {
    const int n = NB * L_TOK;
    __shared__ float red[32];
    __shared__ float s_max, s_sum;
    int tid = threadIdx.x;
    if (tid < DM) g_pooled[tid] = 0.f;
    float m = -1e30f;
    for (int i = tid; i < n; i += 1024) m = fmaxf(m, g_scoreb[i]);
    #pragma unroll
    for (int o = 16; o > 0; o >>= 1) m = fmaxf(m, __shfl_xor_sync(0xffffffffu, m, o));
    if ((tid & 31) == 0) red[tid >> 5] = m;
    __syncthreads();
    if (tid < 32) {
        float v = red[tid];
        #pragma unroll
        for (int o = 16; o > 0; o >>= 1) v = fmaxf(v, __shfl_xor_sync(0xffffffffu, v, o));
        if (tid == 0) s_max = v;
    }
    __syncthreads();
    float m0 = s_max;
    float s = 0.f;
    for (int i = tid; i < n; i += 1024) s += expf(g_scoreb[i] - m0);
    #pragma unroll
    for (int o = 16; o > 0; o >>= 1) s += __shfl_xor_sync(0xffffffffu, s, o);
    if ((tid & 31) == 0) red[tid >> 5] = s;
    __syncthreads();
    if (tid < 32) {
        float v = red[tid];
        #pragma unroll
        for (int o = 16; o > 0; o >>= 1) v += __shfl_xor_sync(0xffffffffu, v, o);
        if (tid == 0) s_sum = v;
    }
    __syncthreads();
    float inv = 1.f / s_sum;
    for (int i = tid; i < n; i += 1024) g_wts[i] = expf(g_scoreb[i] - m0) * inv;
}

// ---------------- pooled: coalesced row-major accumulate + atomics ----------------
#define PBLK 120
__global__ __launch_bounds__(256) void k_pooled() {
    const int total = NB * L_TOK;
    int per = (total + PBLK - 1) / PBLK;
    int g0 = blockIdx.x * per;
    int g1 = g0 + per; if (g1 > total) g1 = total;
    int tid = threadIdx.x;
    float a0 = 0.f, a1 = 0.f;
    for (int g = g0; g < g1; g++) {
        float w = g_wts[g];
        float2 v = *(const float2*)&g_hn[(long long)g * DM + 2 * tid];
        a0 = fmaf(w, v.x, a0);
        a1 = fmaf(w, v.y, a1);
    }
    atomicAdd(&g_pooled[2 * tid], a0);
    atomicAdd(&g_pooled[2 * tid + 1], a1);
}

// ---------------- final classifier + softmax ----------------
__global__ void k_final(const float* __restrict__ cls_w, const float* __restrict__ cls_b,
                        float* __restrict__ out, int out_size) {
    int tid = threadIdx.x;
    int cls = tid >> 5, lane = tid & 31;
    float acc = 0.f;
    for (int d = lane; d < DM; d += 32) acc += g_pooled[d] * cls_w[cls * DM + d];
    #pragma unroll
    for (int o = 16; o > 0; o >>= 1) acc += __shfl_xor_sync(0xffffffffu, acc, o);
    __shared__ float lg[2];
    if (lane == 0) lg[cls] = acc;
    __syncthreads();
    if (tid == 0) {
        float l0 = lg[0] + cls_b[0], l1 = lg[1] + cls_b[1];
        float m = fmaxf(l0, l1);
        float e0 = expf(l0 - m), e1 = expf(l1 - m);
        float s = e0 + e1;
        out[0] = l0;
        out[1] = l1;
        if (out_size >= 4) { out[2] = e0 / s; out[3] = e1 / s; }
    }
}

// ---------------- launch ----------------
static inline void launch_split(const float* src, void* dst, long long npairs) {
    k_split<<<(int)((npairs + 255) / 256), 256>>>(src, (uint2*)dst, npairs);
}

extern "C" void kernel_launch(void* const* d_in, const int* in_sizes, int n_in,
                              void* d_out, int out_size) {
    const float* x        = (const float*)d_in[0];
    const float* fc1_w    = (const float*)d_in[1];
    const float* fc1_b    = (const float*)d_in[2];
    const float* in_proj_w= (const float*)d_in[3];
    const float* conv_w   = (const float*)d_in[4];
    const float* conv_b   = (const float*)d_in[5];
    const float* dt_bias  = (const float*)d_in[6];
    const float* A_log    = (const float*)d_in[7];
    const float* Dh       = (const float*)d_in[8];
    const float* norm_w   = (const float*)d_in[9];
    const float* out_proj_w=(const float*)d_in[10];
    const float* ln_w     = (const float*)d_in[11];
    const float* ln_b     = (const float*)d_in[12];
    const float* attn_w1  = (const float*)d_in[13];
    const float* attn_b1  = (const float*)d_in[14];
    const float* attn_w2  = (const float*)d_in[15];
    const float* attn_b2  = (const float*)d_in[16];
    const float* cls_w    = (const float*)d_in[17];
    const float* cls_b    = (const float*)d_in[18];
    float* out = (float*)d_out;

    void *p_hcur, *p_zx, *p_y, *p_s1;
    void *p_xS, *p_fc1wS, *p_ipwS, *p_opwS, *p_aw1S, *p_hcurS, *p_ySp, *p_hnS;
    cudaGetSymbolAddress(&p_hcur,  g_hcur);
    cudaGetSymbolAddress(&p_zx,    g_zx);
    cudaGetSymbolAddress(&p_y,     g_y);
    cudaGetSymbolAddress(&p_s1,    g_s1);
    cudaGetSymbolAddress(&p_xS,    g_xS);
    cudaGetSymbolAddress(&p_fc1wS, g_fc1wS);
    cudaGetSymbolAddress(&p_ipwS,  g_ipwS);
    cudaGetSymbolAddress(&p_opwS,  g_opwS);
    cudaGetSymbolAddress(&p_aw1S,  g_aw1S);
    cudaGetSymbolAddress(&p_hcurS, g_hcurS);
    cudaGetSymbolAddress(&p_ySp,   g_ySp);
    cudaGetSymbolAddress(&p_hnS,   g_hnS);

    cudaFuncSetAttribute(tgemm, cudaFuncAttributeMaxDynamicSharedMemorySize, TG_SMEM);
    cudaFuncSetAttribute(k_intra_mma, cudaFuncAttributeMaxDynamicSharedMemorySize, SMEM_INTRA_MMA);

    // launches 1-3: splits needed before fc1/in_proj
    launch_split(x,         p_xS,    (long long)L_TOK * 512);
    launch_split(fc1_w,     p_fc1wS, (long long)DM * 512);
    launch_split(in_proj_w, p_ipwS,  (long long)6 * DPROJ * 256);

    // launch 4: fc1 (op=4 fused prep + splits)
    {
        dim3 grid((DM + 127) / 128, (L_TOK + 127) / 128, 1);
        tgemm<<<grid, 256, TG_SMEM>>>((const uint2*)p_xS, 0, (const uint2*)p_fc1wS, 0, fc1_b,
                                      (float*)p_hcur, 0, nullptr, L_TOK, DM, 512, 4, 0);
    }
    // launch 5: zero pad rows
    k_zeropad2<<<(NB * (LP - L_TOK) * DM + 255) / 256, 256>>>();

    for (int j = 0; j < 2; j++) {
        // launch 6 (j=0): in_proj  <- ncu -s 5 lands here
        {
            dim3 g1((DPROJ + 127) / 128, (LP + 127) / 128, NB);
            tgemm<<<g1, 256, TG_SMEM>>>((const uint2*)p_hcurS, (long long)LP * 256,
                                        (const uint2*)p_ipwS, (long long)DPROJ * 256, nullptr,
                                        (float*)p_zx, (long long)LP * DPROJ, nullptr,
                                        LP, DPROJ, 256, 0, j);
        }
        k_convfused<<<dim3(NC, NB), 256>>>(conv_w, conv_b, dt_bias, A_log, j);
        k_intra_mma<<<dim3(NC, NH, NB), 256, SMEM_INTRA_MMA>>>();
        k_rec<<<dim3(NB * NH, 4), 256>>>();
        k_inter_mma<<<dim3(NC, NH, NB), 256>>>(Dh, j);
        k_gate<<<dim3(LP, NB), 256>>>(norm_w, j);
        if (j == 0)
            launch_split(out_proj_w, p_opwS, (long long)6 * DM * 512);
        // out_proj + residual accumulate (+ fused split of updated hcur)
        {
            dim3 g2((DM + 127) / 128, (LP + 127) / 128, NB);
            tgemm<<<g2, 256, TG_SMEM>>>((const uint2*)p_ySp, (long long)LP * 512,
                                        (const uint2*)p_opwS, (long long)DM * 512, nullptr,
                                        (float*)p_hcur, (long long)LP * DM,
                                        (j == 0) ? (uint2*)p_hcurS : nullptr,
                                        LP, DM, 512, 1, j);
        }
    }

    // final head
    k_ln<<<NB * L_TOK, 256>>>(ln_w, ln_b);
    launch_split(attn_w1, p_aw1S, (long long)128 * 256);
    {
        dim3 ga(1, (NB * L_TOK + 127) / 128, 1);
        tgemm<<<ga, 256, TG_SMEM>>>((const uint2*)p_hnS, 0, (const uint2*)p_aw1S, 0, attn_b1,
                                    (float*)p_s1, 0, nullptr, NB * L_TOK, 128, 256, 3, 0);
    }
    k_score<<<NB * L_TOK, 128>>>(attn_w2, attn_b2);
    k_softmax<<<1, 1024>>>();
    k_pooled<<<PBLK, 256>>>();
    k_final<<<1, 64>>>(cls_w, cls_b, out, out_size);
}